// round 1
// baseline (speedup 1.0000x reference)
#include <cuda_runtime.h>
#include <cuda_bf16.h>
#include <cstdint>

// ---------------------------------------------------------------------------
// JanossyPoolingImproper: out[n] = (sum_p MLP(concat_j h[idx[n, perm_p[j]]])) @ Wo + bo
// Round 1: correct fp32 baseline. Multi-kernel pipeline:
//   detect idx dtype -> gather X[3N,512] -> 3x (GEMM 512x512 + bias + relu) -> pooled proj
// ---------------------------------------------------------------------------

#define H_DIM 512
#define F_DIM 128
#define MAX_N 100000
#define MAX_M (3 * MAX_N)

__constant__ int c_perms[3][4] = {{0, 1, 2, 3}, {2, 1, 3, 0}, {3, 1, 0, 2}};

// Scratch (no cudaMalloc allowed): two ping-pong activation buffers, 614.4 MB each.
__device__ float g_bufA[(size_t)MAX_M * H_DIM];
__device__ float g_bufB[(size_t)MAX_M * H_DIM];
__device__ int g_idx64_flag;

// ---------------------------------------------------------------------------
// Detect whether idx is int64 or int32. If the buffer really holds int64,
// every entry (read as int64) is a valid index in [0, n_h). If it holds int32,
// an int64 read combines two int32 values -> >= 2^32 almost surely.
// ---------------------------------------------------------------------------
__global__ void detect_idx_kernel(const long long* __restrict__ idx64, int n_h) {
    long long v = idx64[threadIdx.x];
    int ok = (v >= 0 && v < (long long)n_h) ? 1 : 0;
    int all = __syncthreads_and(ok);
    if (threadIdx.x == 0) g_idx64_flag = all;
}

// ---------------------------------------------------------------------------
// Gather: X[p*N + n, j*128 + c] = h[idx[n, perm_p[j]], c]
// One thread per float4. Row layout of X is tid-major so the store is coalesced.
// h (25.6MB) stays L2-resident across the whole gather.
// ---------------------------------------------------------------------------
__global__ void gather_kernel(const float* __restrict__ h,
                              const void* __restrict__ idx,
                              int N, int n_h) {
    long long tid = (long long)blockIdx.x * blockDim.x + threadIdx.x;
    long long total = (long long)3 * N * (H_DIM / 4);
    if (tid >= total) return;
    int c4 = (int)(tid & 127);       // float4 index within the 512-wide row
    long long r = tid >> 7;          // row in [0, 3N)
    int n = (int)(r % N);
    int p = (int)(r / N);
    int j = c4 >> 5;                 // which 128-feature block (32 float4 each)
    int slot = c_perms[p][j];
    long long nb;
    if (g_idx64_flag) {
        nb = ((const long long*)idx)[(long long)n * 4 + slot];
    } else {
        nb = (long long)((const int*)idx)[n * 4 + slot];
    }
    const float4* src = (const float4*)(h + nb * F_DIM);
    ((float4*)g_bufA)[tid] = __ldg(&src[c4 & 31]);
}

// ---------------------------------------------------------------------------
// C[M,512] = relu(A[M,512] @ W[512,512] + bias)
// Classic register-blocked sgemm: 128x128 block tile, BK=8, 256 threads,
// 8x8 micro-tile per thread.
// ---------------------------------------------------------------------------
__global__ __launch_bounds__(256) void gemm_bias_relu_kernel(
    const float* __restrict__ A, const float* __restrict__ W,
    const float* __restrict__ bias, float* __restrict__ C, int M)
{
    const int K = H_DIM, N = H_DIM;
    __shared__ float As[8][128];   // transposed A tile: As[k][m]
    __shared__ float Bs[8][128];   // Bs[k][n]

    int bm = blockIdx.y * 128;
    int bn = blockIdx.x * 128;
    int tid = threadIdx.x;
    int tx = tid & 15;             // 16 threads across N
    int ty = tid >> 4;             // 16 threads across M

    float acc[8][8];
#pragma unroll
    for (int i = 0; i < 8; i++)
#pragma unroll
        for (int j = 0; j < 8; j++) acc[i][j] = 0.0f;

    // A tile load mapping: thread -> one float4 of the [128 x 8] tile
    int a_r = tid >> 1;            // 0..127
    int a_c = (tid & 1) * 4;       // 0 or 4
    // B tile load mapping: thread -> one float4 of the [8 x 128] tile
    int b_r = tid >> 5;            // 0..7
    int b_c = (tid & 31) * 4;      // 0..124

    long long arow = (long long)bm + a_r;
    const float* a_src = A + arow * K + a_c;
    const float* b_src = W + (long long)b_r * N + bn + b_c;

    for (int k0 = 0; k0 < K; k0 += 8) {
        float4 av;
        if (arow < M) av = *(const float4*)(a_src + k0);
        else          av = make_float4(0.f, 0.f, 0.f, 0.f);
        float4 bv = *(const float4*)(b_src + (long long)k0 * N);

        As[a_c + 0][a_r] = av.x;
        As[a_c + 1][a_r] = av.y;
        As[a_c + 2][a_r] = av.z;
        As[a_c + 3][a_r] = av.w;
        *(float4*)&Bs[b_r][b_c] = bv;
        __syncthreads();

#pragma unroll
        for (int k = 0; k < 8; k++) {
            float ra[8], rb[8];
            *(float4*)&ra[0] = *(const float4*)&As[k][ty * 8 + 0];
            *(float4*)&ra[4] = *(const float4*)&As[k][ty * 8 + 4];
            *(float4*)&rb[0] = *(const float4*)&Bs[k][tx * 8 + 0];
            *(float4*)&rb[4] = *(const float4*)&Bs[k][tx * 8 + 4];
#pragma unroll
            for (int i = 0; i < 8; i++)
#pragma unroll
                for (int j = 0; j < 8; j++)
                    acc[i][j] += ra[i] * rb[j];
        }
        __syncthreads();
    }

    // Epilogue: bias + relu, vectorized stores
    float bvals[8];
#pragma unroll
    for (int j = 0; j < 8; j++) bvals[j] = __ldg(&bias[bn + tx * 8 + j]);

#pragma unroll
    for (int i = 0; i < 8; i++) {
        long long row = (long long)bm + ty * 8 + i;
        if (row >= M) continue;
        float* crow = C + row * N + bn + tx * 8;
        float4 v0, v1;
        v0.x = fmaxf(acc[i][0] + bvals[0], 0.f);
        v0.y = fmaxf(acc[i][1] + bvals[1], 0.f);
        v0.z = fmaxf(acc[i][2] + bvals[2], 0.f);
        v0.w = fmaxf(acc[i][3] + bvals[3], 0.f);
        v1.x = fmaxf(acc[i][4] + bvals[4], 0.f);
        v1.y = fmaxf(acc[i][5] + bvals[5], 0.f);
        v1.z = fmaxf(acc[i][6] + bvals[6], 0.f);
        v1.w = fmaxf(acc[i][7] + bvals[7], 0.f);
        *(float4*)(crow + 0) = v0;
        *(float4*)(crow + 4) = v1;
    }
}

// ---------------------------------------------------------------------------
// out[n, :2] = (Y[n] + Y[N+n] + Y[2N+n]) @ Wo[512,2] + bo[2]
// One warp per sample; coalesced strided reads + warp reduction.
// ---------------------------------------------------------------------------
__global__ void final_kernel(const float* __restrict__ Y,
                             const float* __restrict__ Wo,
                             const float* __restrict__ bo,
                             float* __restrict__ out, int N) {
    int warp = (int)(((long long)blockIdx.x * blockDim.x + threadIdx.x) >> 5);
    int lane = threadIdx.x & 31;
    if (warp >= N) return;
    const float* y0 = Y + (long long)warp * H_DIM;
    const float* y1 = Y + (long long)(warp + N) * H_DIM;
    const float* y2 = Y + (long long)(warp + 2 * N) * H_DIM;
    float s0 = 0.f, s1 = 0.f;
#pragma unroll
    for (int c = lane; c < H_DIM; c += 32) {
        float v = y0[c] + y1[c] + y2[c];
        s0 += v * __ldg(&Wo[c * 2 + 0]);
        s1 += v * __ldg(&Wo[c * 2 + 1]);
    }
#pragma unroll
    for (int off = 16; off; off >>= 1) {
        s0 += __shfl_down_sync(0xFFFFFFFFu, s0, off);
        s1 += __shfl_down_sync(0xFFFFFFFFu, s1, off);
    }
    if (lane == 0) {
        out[(long long)warp * 2 + 0] = s0 + __ldg(&bo[0]);
        out[(long long)warp * 2 + 1] = s1 + __ldg(&bo[1]);
    }
}

// ---------------------------------------------------------------------------
extern "C" void kernel_launch(void* const* d_in, const int* in_sizes, int n_in,
                              void* d_out, int out_size) {
    const float* h   = (const float*)d_in[0];
    const void*  idx = d_in[1];
    const float* W1  = (const float*)d_in[2];
    const float* b1  = (const float*)d_in[3];
    const float* W2  = (const float*)d_in[4];
    const float* b2  = (const float*)d_in[5];
    const float* W3  = (const float*)d_in[6];
    const float* b3  = (const float*)d_in[7];
    const float* Wo  = (const float*)d_in[8];
    const float* bo  = (const float*)d_in[9];
    float* out = (float*)d_out;

    int N   = in_sizes[1] / 4;          // 100000
    int n_h = in_sizes[0] / F_DIM;      // 50000
    int M   = 3 * N;                    // 300000

    float* bufA = nullptr;
    float* bufB = nullptr;
    cudaGetSymbolAddress((void**)&bufA, g_bufA);
    cudaGetSymbolAddress((void**)&bufB, g_bufB);

    // 1. dtype detection for idx (int32 vs int64)
    detect_idx_kernel<<<1, 256>>>((const long long*)idx, n_h);

    // 2. gather X[3N,512] into bufA
    long long total = (long long)3 * N * (H_DIM / 4);
    int gblocks = (int)((total + 255) / 256);
    gather_kernel<<<gblocks, 256>>>(h, idx, N, n_h);

    // 3. three GEMM + bias + relu layers (ping-pong bufA <-> bufB)
    dim3 ggrid(H_DIM / 128, (M + 127) / 128);
    gemm_bias_relu_kernel<<<ggrid, 256>>>(bufA, W1, b1, bufB, M);
    gemm_bias_relu_kernel<<<ggrid, 256>>>(bufB, W2, b2, bufA, M);
    gemm_bias_relu_kernel<<<ggrid, 256>>>(bufA, W3, b3, bufB, M);

    // 4. Janossy sum over permutations + output projection
    int fwarps_per_block = 256 / 32;
    int fblocks = (N + fwarps_per_block - 1) / fwarps_per_block;
    final_kernel<<<fblocks, 256>>>(bufB, Wo, bo, out, N);
}

// round 3
// speedup vs baseline: 3.5735x; 3.5735x over previous
#include <cuda_runtime.h>
#include <cstdint>

// ---------------------------------------------------------------------------
// JanossyPoolingImproper — Round 3: mma.sync tf32 GEMMs (tcgen05 unavailable:
// harness PTX target is compute_103, not compute_103a).
// Pipeline: detect idx dtype -> transpose+rna W1..W3 -> gather+rna X[3N,512]
//           -> 3x mma.sync tf32 GEMM (cp.async double buffer, bias+relu+rna)
//           -> Janossy-sum + 512->2 projection (fp32).
// All GEMM operand buffers hold rna-rounded tf32 values in fp32 containers, so
// the hardware's fp32->tf32 truncation inside mma.sync is exact (no bias).
// ---------------------------------------------------------------------------

#define H_DIM 512
#define F_DIM 128
#define MAX_N 100000
#define MAX_M (3 * MAX_N)

#define KC 32                     // K per SMEM stage
#define NSTAGE (H_DIM / KC)       // 16
#define ROWSTRIDE 36              // floats per SMEM row (32 + 4 pad)
#define TILE_F (128 * ROWSTRIDE)  // 4608 floats per tile buffer
#define TILE_B (TILE_F * 4)       // 18432 bytes
#define SMEM_BYTES (4 * TILE_B)   // A0,A1,B0,B1 = 73728

__constant__ int c_perms[3][4] = {{0,1,2,3},{2,1,3,0},{3,1,0,2}};

// Scratch (no cudaMalloc allowed)
__device__ float g_bufA[(size_t)MAX_M * H_DIM];
__device__ float g_bufB[(size_t)MAX_M * H_DIM];
__device__ float g_Wt[3][H_DIM * H_DIM];
__device__ int   g_idx64_flag;

// ---------------------------- helpers -------------------------------------
__device__ __forceinline__ uint32_t smem_u32(const void* p) {
    uint32_t a;
    asm("{ .reg .u64 t; cvta.to.shared.u64 t, %1; cvt.u32.u64 %0, t; }" : "=r"(a) : "l"(p));
    return a;
}
__device__ __forceinline__ float rna_tf32(float f) {
    uint32_t r;
    asm("cvt.rna.tf32.f32 %0, %1;" : "=r"(r) : "f"(f));
    return __uint_as_float(r);
}
__device__ __forceinline__ void cp16(uint32_t dst, const void* src, bool pred) {
    int bytes = pred ? 16 : 0;
    asm volatile("cp.async.ca.shared.global [%0], [%1], 16, %2;"
                 :: "r"(dst), "l"(src), "r"(bytes) : "memory");
}
__device__ __forceinline__ void cp_commit() {
    asm volatile("cp.async.commit_group;" ::: "memory");
}
template <int N>
__device__ __forceinline__ void cp_wait() {
    asm volatile("cp.async.wait_group %0;" :: "n"(N) : "memory");
}
__device__ __forceinline__ void mma_tf32(float* c, const uint32_t* a, const uint32_t* b) {
    asm volatile(
        "mma.sync.aligned.m16n8k8.row.col.f32.tf32.tf32.f32 "
        "{%0,%1,%2,%3}, {%4,%5,%6,%7}, {%8,%9}, {%0,%1,%2,%3};"
        : "+f"(c[0]), "+f"(c[1]), "+f"(c[2]), "+f"(c[3])
        : "r"(a[0]), "r"(a[1]), "r"(a[2]), "r"(a[3]), "r"(b[0]), "r"(b[1]));
}

// ---------------------------------------------------------------------------
__global__ void detect_idx_kernel(const long long* __restrict__ idx64, int n_h) {
    long long v = idx64[threadIdx.x];
    int ok = (v >= 0 && v < (long long)n_h) ? 1 : 0;
    int all = __syncthreads_and(ok);
    if (threadIdx.x == 0) g_idx64_flag = all;
}

// W[k][n] -> Wt[n][k] with rna tf32 rounding
__global__ void transpose512_kernel(const float* __restrict__ W, float* __restrict__ Wt) {
    __shared__ float t[32][33];
    int x = blockIdx.x * 32 + threadIdx.x;
    int y0 = blockIdx.y * 32;
#pragma unroll
    for (int i = threadIdx.y; i < 32; i += 8)
        t[i][threadIdx.x] = W[(y0 + i) * H_DIM + x];
    __syncthreads();
    int nx = blockIdx.y * 32 + threadIdx.x;
    int ny0 = blockIdx.x * 32;
#pragma unroll
    for (int i = threadIdx.y; i < 32; i += 8)
        Wt[(ny0 + i) * H_DIM + nx] = rna_tf32(t[threadIdx.x][i]);
}

// ---------------------------------------------------------------------------
__global__ void gather_kernel(const float* __restrict__ h,
                              const void* __restrict__ idx,
                              int N, int n_h) {
    long long tid = (long long)blockIdx.x * blockDim.x + threadIdx.x;
    long long total = (long long)3 * N * (H_DIM / 4);
    if (tid >= total) return;
    int c4 = (int)(tid & 127);
    long long r = tid >> 7;
    int n = (int)(r % N);
    int p = (int)(r / N);
    int j = c4 >> 5;
    int slot = c_perms[p][j];
    long long nb;
    if (g_idx64_flag) nb = ((const long long*)idx)[(long long)n * 4 + slot];
    else              nb = (long long)((const int*)idx)[n * 4 + slot];
    const float4* src = (const float4*)(h + nb * F_DIM);
    float4 v = __ldg(&src[c4 & 31]);
    v.x = rna_tf32(v.x); v.y = rna_tf32(v.y);
    v.z = rna_tf32(v.z); v.w = rna_tf32(v.w);
    ((float4*)g_bufA)[tid] = v;
}

// ---------------------------------------------------------------------------
// C[M,512] = relu(A[M,512] @ Wt^T + bias)  via mma.sync m16n8k8 tf32.
// CTA tile 128(M) x 128(N); warp tile 64x32 (4x4 frags); K staged by 32,
// cp.async double buffered. round_out: rna-round outputs (inputs of next GEMM).
// ---------------------------------------------------------------------------
__global__ __launch_bounds__(256, 2) void gemm_mma_kernel(
    const float* __restrict__ A, const float* __restrict__ Wt,
    const float* __restrict__ bias, float* __restrict__ C,
    int M, int round_out)
{
    extern __shared__ char smem[];
    float* As = (float*)smem;                      // [2][128][36]
    float* Bs = (float*)(smem + 2 * TILE_B);       // [2][128][36]
    uint32_t sA = smem_u32(smem);
    uint32_t sB = sA + 2 * TILE_B;

    int tid = threadIdx.x;
    int lane = tid & 31, wid = tid >> 5;
    int wm = wid >> 2, wn = wid & 3;               // warp -> (2 x 4) layout
    int g = lane >> 2, t = lane & 3;
    int bm = blockIdx.x * 128;
    int bn = blockIdx.y * 128;

    float acc[4][4][4];
#pragma unroll
    for (int i = 0; i < 4; i++)
#pragma unroll
        for (int j = 0; j < 4; j++)
#pragma unroll
            for (int r = 0; r < 4; r++) acc[i][j][r] = 0.0f;

    // ---- stage loader: A tile [128 x 32], B tile [128n x 32k] ----
    auto load_stage = [&](int s) {
        int buf = s & 1;
        int k0 = s * KC;
#pragma unroll
        for (int i = 0; i < 4; i++) {
            int idx = tid + i * 256;
            int row = idx >> 3, q = idx & 7;
            uint32_t dst = sA + buf * TILE_B + (uint32_t)(row * ROWSTRIDE * 4 + q * 16);
            const float* src = A + (size_t)(bm + row) * H_DIM + k0 + q * 4;
            cp16(dst, src, (bm + row) < M);
        }
#pragma unroll
        for (int i = 0; i < 4; i++) {
            int idx = tid + i * 256;
            int row = idx >> 3, q = idx & 7;
            uint32_t dst = sB + buf * TILE_B + (uint32_t)(row * ROWSTRIDE * 4 + q * 16);
            const float* src = Wt + (size_t)(bn + row) * H_DIM + k0 + q * 4;
            cp16(dst, src, true);
        }
        cp_commit();
    };

    load_stage(0);

    for (int s = 0; s < NSTAGE; s++) {
        if (s + 1 < NSTAGE) { load_stage(s + 1); cp_wait<1>(); }
        else                { cp_wait<0>(); }
        __syncthreads();

        const float* a_t = As + (s & 1) * TILE_F;
        const float* b_t = Bs + (s & 1) * TILE_F;
#pragma unroll
        for (int ks = 0; ks < 4; ks++) {
            int k = ks * 8;
            uint32_t af[4][4];
#pragma unroll
            for (int mf = 0; mf < 4; mf++) {
                int r = wm * 64 + mf * 16 + g;
                af[mf][0] = __float_as_uint(a_t[r * ROWSTRIDE + k + t]);
                af[mf][1] = __float_as_uint(a_t[(r + 8) * ROWSTRIDE + k + t]);
                af[mf][2] = __float_as_uint(a_t[r * ROWSTRIDE + k + t + 4]);
                af[mf][3] = __float_as_uint(a_t[(r + 8) * ROWSTRIDE + k + t + 4]);
            }
            uint32_t bf[4][2];
#pragma unroll
            for (int nf = 0; nf < 4; nf++) {
                int n = wn * 32 + nf * 8 + g;
                bf[nf][0] = __float_as_uint(b_t[n * ROWSTRIDE + k + t]);
                bf[nf][1] = __float_as_uint(b_t[n * ROWSTRIDE + k + t + 4]);
            }
#pragma unroll
            for (int mf = 0; mf < 4; mf++)
#pragma unroll
                for (int nf = 0; nf < 4; nf++)
                    mma_tf32(acc[mf][nf], af[mf], bf[nf]);
        }
        __syncthreads();
    }

    // ---- epilogue: bias + relu (+ rna for next layer), float2 stores ----
#pragma unroll
    for (int nf = 0; nf < 4; nf++) {
        int col = bn + wn * 32 + nf * 8 + 2 * t;
        float2 b2 = *(const float2*)(bias + col);
#pragma unroll
        for (int mf = 0; mf < 4; mf++) {
            int row0 = bm + wm * 64 + mf * 16 + g;
            float v0 = fmaxf(acc[mf][nf][0] + b2.x, 0.f);
            float v1 = fmaxf(acc[mf][nf][1] + b2.y, 0.f);
            float v2 = fmaxf(acc[mf][nf][2] + b2.x, 0.f);
            float v3 = fmaxf(acc[mf][nf][3] + b2.y, 0.f);
            if (round_out) {
                v0 = rna_tf32(v0); v1 = rna_tf32(v1);
                v2 = rna_tf32(v2); v3 = rna_tf32(v3);
            }
            if (row0 < M)
                *(float2*)(C + (size_t)row0 * H_DIM + col) = make_float2(v0, v1);
            if (row0 + 8 < M)
                *(float2*)(C + (size_t)(row0 + 8) * H_DIM + col) = make_float2(v2, v3);
        }
    }
}

// ---------------------------------------------------------------------------
__global__ void final_kernel(const float* __restrict__ Y,
                             const float* __restrict__ Wo,
                             const float* __restrict__ bo,
                             float* __restrict__ out, int N) {
    int warp = (int)(((long long)blockIdx.x * blockDim.x + threadIdx.x) >> 5);
    int lane = threadIdx.x & 31;
    if (warp >= N) return;
    const float* y0 = Y + (long long)warp * H_DIM;
    const float* y1 = Y + (long long)(warp + N) * H_DIM;
    const float* y2 = Y + (long long)(warp + 2 * N) * H_DIM;
    float s0 = 0.f, s1 = 0.f;
#pragma unroll
    for (int c = lane; c < H_DIM; c += 32) {
        float v = y0[c] + y1[c] + y2[c];
        s0 += v * __ldg(&Wo[c * 2 + 0]);
        s1 += v * __ldg(&Wo[c * 2 + 1]);
    }
#pragma unroll
    for (int off = 16; off; off >>= 1) {
        s0 += __shfl_down_sync(0xFFFFFFFFu, s0, off);
        s1 += __shfl_down_sync(0xFFFFFFFFu, s1, off);
    }
    if (lane == 0) {
        out[(long long)warp * 2 + 0] = s0 + __ldg(&bo[0]);
        out[(long long)warp * 2 + 1] = s1 + __ldg(&bo[1]);
    }
}

// ---------------------------------------------------------------------------
extern "C" void kernel_launch(void* const* d_in, const int* in_sizes, int n_in,
                              void* d_out, int out_size) {
    const float* h   = (const float*)d_in[0];
    const void*  idx = d_in[1];
    const float* W1  = (const float*)d_in[2];
    const float* b1  = (const float*)d_in[3];
    const float* W2  = (const float*)d_in[4];
    const float* b2  = (const float*)d_in[5];
    const float* W3  = (const float*)d_in[6];
    const float* b3  = (const float*)d_in[7];
    const float* Wo  = (const float*)d_in[8];
    const float* bo  = (const float*)d_in[9];
    float* out = (float*)d_out;

    int N   = in_sizes[1] / 4;
    int n_h = in_sizes[0] / F_DIM;
    int M   = 3 * N;

    float* bufA = nullptr; float* bufB = nullptr; float* wt = nullptr;
    cudaGetSymbolAddress((void**)&bufA, g_bufA);
    cudaGetSymbolAddress((void**)&bufB, g_bufB);
    cudaGetSymbolAddress((void**)&wt, g_Wt);
    float* Wt1 = wt;
    float* Wt2 = wt + H_DIM * H_DIM;
    float* Wt3 = wt + 2 * H_DIM * H_DIM;

    cudaFuncSetAttribute(gemm_mma_kernel,
                         cudaFuncAttributeMaxDynamicSharedMemorySize, SMEM_BYTES);

    detect_idx_kernel<<<1, 256>>>((const long long*)idx, n_h);

    dim3 tb(32, 8), tg(16, 16);
    transpose512_kernel<<<tg, tb>>>(W1, Wt1);
    transpose512_kernel<<<tg, tb>>>(W2, Wt2);
    transpose512_kernel<<<tg, tb>>>(W3, Wt3);

    long long total = (long long)3 * N * (H_DIM / 4);
    int gblocks = (int)((total + 255) / 256);
    gather_kernel<<<gblocks, 256>>>(h, idx, N, n_h);

    int mtiles = (M + 127) / 128;
    dim3 ggrid(mtiles, H_DIM / 128);
    gemm_mma_kernel<<<ggrid, 256, SMEM_BYTES>>>(bufA, Wt1, b1, bufB, M, 1);
    gemm_mma_kernel<<<ggrid, 256, SMEM_BYTES>>>(bufB, Wt2, b2, bufA, M, 1);
    gemm_mma_kernel<<<ggrid, 256, SMEM_BYTES>>>(bufA, Wt3, b3, bufB, M, 0);

    int fblocks = (N + 7) / 8;
    final_kernel<<<fblocks, 256>>>(bufB, Wo, bo, out, N);
}

// round 4
// speedup vs baseline: 6.0339x; 1.6885x over previous
#include <cuda_runtime.h>
#include <cuda_fp16.h>
#include <cstdint>

// ---------------------------------------------------------------------------
// JanossyPoolingImproper — Round 4: fp16 mma.sync m16n8k16 (fp32 accum).
// detect idx dtype -> h:f32->f16 -> W1..3 transpose->f16 ->
//   GEMM1 (gather fused into A loader, h16 via idx) -> Y0 (f16)
//   GEMM2: Y0 -> Y1   GEMM3: Y1 -> Y0
//   final: Janossy sum over perms + 512->2 projection (fp32).
// fp16 e5m10 has the same 10-bit mantissa as tf32; operands RN-rounded,
// accumulation fp32 -> same error budget as the passing tf32 version.
// ---------------------------------------------------------------------------

#define H_DIM 512
#define F_DIM 128
#define MAX_N 100000
#define MAX_M (3 * MAX_N)
#define MAX_NH 50000

#define KC 32                     // K per SMEM stage (halves)
#define NSTAGE (H_DIM / KC)       // 16
#define ROWB 80                   // bytes per SMEM row: 64 data + 16 pad
#define TILE_B (128 * ROWB)       // 10240 bytes per tile buffer

__constant__ int c_perms[3][4] = {{0,1,2,3},{2,1,3,0},{3,1,0,2}};

// Scratch (no cudaMalloc allowed)
__device__ __half g_Y0[(size_t)MAX_M * H_DIM];
__device__ __half g_Y1[(size_t)MAX_M * H_DIM];
__device__ __half g_h16[(size_t)MAX_NH * F_DIM];
__device__ __half g_Wt16[3][H_DIM * H_DIM];
__device__ int    g_idx64_flag;

// ---------------------------- helpers -------------------------------------
__device__ __forceinline__ uint32_t smem_u32(const void* p) {
    uint32_t a;
    asm("{ .reg .u64 t; cvta.to.shared.u64 t, %1; cvt.u32.u64 %0, t; }" : "=r"(a) : "l"(p));
    return a;
}
__device__ __forceinline__ void cp16(uint32_t dst, const void* src, bool pred) {
    int bytes = pred ? 16 : 0;
    asm volatile("cp.async.ca.shared.global [%0], [%1], 16, %2;"
                 :: "r"(dst), "l"(src), "r"(bytes) : "memory");
}
__device__ __forceinline__ void cp_commit() {
    asm volatile("cp.async.commit_group;" ::: "memory");
}
template <int N>
__device__ __forceinline__ void cp_wait() {
    asm volatile("cp.async.wait_group %0;" :: "n"(N) : "memory");
}
__device__ __forceinline__ void ldm_x4(uint32_t* r, uint32_t addr) {
    asm volatile("ldmatrix.sync.aligned.m8n8.x4.shared.b16 {%0,%1,%2,%3}, [%4];"
                 : "=r"(r[0]), "=r"(r[1]), "=r"(r[2]), "=r"(r[3]) : "r"(addr));
}
__device__ __forceinline__ void mma_fp16(float* c, const uint32_t* a, const uint32_t* b) {
    asm volatile(
        "mma.sync.aligned.m16n8k16.row.col.f32.f16.f16.f32 "
        "{%0,%1,%2,%3}, {%4,%5,%6,%7}, {%8,%9}, {%0,%1,%2,%3};"
        : "+f"(c[0]), "+f"(c[1]), "+f"(c[2]), "+f"(c[3])
        : "r"(a[0]), "r"(a[1]), "r"(a[2]), "r"(a[3]), "r"(b[0]), "r"(b[1]));
}

// ---------------------------------------------------------------------------
__global__ void detect_idx_kernel(const long long* __restrict__ idx64, int n_h) {
    long long v = idx64[threadIdx.x];
    int ok = (v >= 0 && v < (long long)n_h) ? 1 : 0;
    int all = __syncthreads_and(ok);
    if (threadIdx.x == 0) g_idx64_flag = all;
}

// h fp32 -> fp16 (RN)
__global__ void convert_h_kernel(const float* __restrict__ h, int total4) {
    int tid = blockIdx.x * blockDim.x + threadIdx.x;
    if (tid >= total4) return;
    float4 v = ((const float4*)h)[tid];
    __half2 a = __floats2half2_rn(v.x, v.y);
    __half2 b = __floats2half2_rn(v.z, v.w);
    ((__half2*)g_h16)[tid * 2 + 0] = a;
    ((__half2*)g_h16)[tid * 2 + 1] = b;
}

// W[k][n] -> Wt16[n][k] fp16 (RN)
__global__ void transpose512h_kernel(const float* __restrict__ W, __half* __restrict__ Wt) {
    __shared__ float t[32][33];
    int x = blockIdx.x * 32 + threadIdx.x;
    int y0 = blockIdx.y * 32;
#pragma unroll
    for (int i = threadIdx.y; i < 32; i += 8)
        t[i][threadIdx.x] = W[(y0 + i) * H_DIM + x];
    __syncthreads();
    int nx = blockIdx.y * 32 + threadIdx.x;
    int ny0 = blockIdx.x * 32;
#pragma unroll
    for (int i = threadIdx.y; i < 32; i += 8)
        Wt[(ny0 + i) * H_DIM + nx] = __float2half_rn(t[threadIdx.x][i]);
}

// ---------------------------------------------------------------------------
// C[M,512] = relu(A[M,512] @ Wt^T + bias), fp16 mma.sync m16n8k16, f32 accum.
// CTA tile 128x128; 8 warps as 2(M) x 4(N); warp tile 64x32 (4x4 m16n8k16).
// gather_mode=1: layer 1 -- A rows come from g_h16 via idx/perm (X never
// materialized). gather_mode=0: A is a dense fp16 activation buffer.
// ---------------------------------------------------------------------------
__global__ __launch_bounds__(256, 2) void gemm_h_kernel(
    const __half* __restrict__ Ah, const void* __restrict__ idx,
    const __half* __restrict__ Wt, const float* __restrict__ bias,
    __half* __restrict__ C, int M, int Nsamp, int gather_mode)
{
    __shared__ char smem[4 * TILE_B];     // A0 A1 B0 B1
    uint32_t sA = smem_u32(smem);
    uint32_t sB = sA + 2 * TILE_B;

    int tid = threadIdx.x;
    int lane = tid & 31, wid = tid >> 5;
    int wm = wid >> 2, wn = wid & 3;
    int g = lane >> 2, t = lane & 3;
    int bm = blockIdx.x * 128;
    int bn = blockIdx.y * 128;

    // ---- per-thread loader rows (fixed across stages) ----
    // A tasks: 512 = 128 rows x 4 chunks; thread does tasks tid, tid+256.
    int lrow[2]; bool lval[2]; int lp[2];
    long long lnb[2][4];
    int chunk = tid & 3;
#pragma unroll
    for (int i = 0; i < 2; i++) {
        int row = (tid >> 2) + i * 64;
        int rg = bm + row;
        lrow[i] = row;
        lval[i] = rg < M;
        if (gather_mode) {
            int rc = lval[i] ? rg : 0;
            int p = (rc >= 2 * Nsamp) ? 2 : (rc >= Nsamp ? 1 : 0);
            int n = rc - p * Nsamp;
            lp[i] = p;
            if (g_idx64_flag) {
#pragma unroll
                for (int s = 0; s < 4; s++)
                    lnb[i][s] = ((const long long*)idx)[(long long)n * 4 + s];
            } else {
#pragma unroll
                for (int s = 0; s < 4; s++)
                    lnb[i][s] = (long long)((const int*)idx)[n * 4 + s];
            }
        }
    }

    auto load_stage = [&](int s) {
        int buf = s & 1;
        int k0 = s * KC;
        // A tile
#pragma unroll
        for (int i = 0; i < 2; i++) {
            uint32_t dst = sA + buf * TILE_B + (uint32_t)(lrow[i] * ROWB + chunk * 16);
            const __half* src;
            if (gather_mode) {
                int j = s >> 2;                      // 128-col block
                int slot = c_perms[lp[i]][j];
                src = g_h16 + lnb[i][slot] * F_DIM + (k0 & 127) + chunk * 8;
            } else {
                src = Ah + (size_t)(bm + lrow[i]) * H_DIM + k0 + chunk * 8;
            }
            cp16(dst, src, lval[i]);
        }
        // B tile (Wt rows bn..bn+127)
#pragma unroll
        for (int i = 0; i < 2; i++) {
            int row = (tid >> 2) + i * 64;
            uint32_t dst = sB + buf * TILE_B + (uint32_t)(row * ROWB + chunk * 16);
            const __half* src = Wt + (size_t)(bn + row) * H_DIM + k0 + chunk * 8;
            cp16(dst, src, true);
        }
        cp_commit();
    };

    float acc[4][4][4];
#pragma unroll
    for (int i = 0; i < 4; i++)
#pragma unroll
        for (int j = 0; j < 4; j++)
#pragma unroll
            for (int r = 0; r < 4; r++) acc[i][j][r] = 0.0f;

    // ldmatrix per-lane address components
    int a_row_off = (lane & 7) + ((lane >> 3) & 1) * 8;   // + mf*16 + wm*64
    int a_col_off = (lane >> 4) * 8;                      // + k
    int b_row_off = (lane & 7) + (lane >> 4) * 8;         // + nfp*16 + wn*32
    int b_col_off = ((lane >> 3) & 1) * 8;                // + k

    load_stage(0);

    for (int s = 0; s < NSTAGE; s++) {
        if (s + 1 < NSTAGE) { load_stage(s + 1); cp_wait<1>(); }
        else                { cp_wait<0>(); }
        __syncthreads();

        uint32_t aT = sA + (s & 1) * TILE_B;
        uint32_t bT = sB + (s & 1) * TILE_B;
#pragma unroll
        for (int ks = 0; ks < 2; ks++) {
            int k = ks * 16;
            uint32_t af[4][4], bf[4][2];
#pragma unroll
            for (int mf = 0; mf < 4; mf++) {
                int row = wm * 64 + mf * 16 + a_row_off;
                ldm_x4(af[mf], aT + (uint32_t)(row * ROWB + (k + a_col_off) * 2));
            }
#pragma unroll
            for (int nfp = 0; nfp < 2; nfp++) {
                uint32_t r4[4];
                int row = wn * 32 + nfp * 16 + b_row_off;
                ldm_x4(r4, bT + (uint32_t)(row * ROWB + (k + b_col_off) * 2));
                bf[nfp * 2 + 0][0] = r4[0]; bf[nfp * 2 + 0][1] = r4[1];
                bf[nfp * 2 + 1][0] = r4[2]; bf[nfp * 2 + 1][1] = r4[3];
            }
#pragma unroll
            for (int mf = 0; mf < 4; mf++)
#pragma unroll
                for (int nf = 0; nf < 4; nf++)
                    mma_fp16(acc[mf][nf], af[mf], bf[nf]);
        }
        __syncthreads();
    }

    // ---- epilogue: bias + relu -> fp16 store ----
#pragma unroll
    for (int nf = 0; nf < 4; nf++) {
        int col = bn + wn * 32 + nf * 8 + 2 * t;
        float2 b2 = *(const float2*)(bias + col);
#pragma unroll
        for (int mf = 0; mf < 4; mf++) {
            int row0 = bm + wm * 64 + mf * 16 + g;
            float v0 = fmaxf(acc[mf][nf][0] + b2.x, 0.f);
            float v1 = fmaxf(acc[mf][nf][1] + b2.y, 0.f);
            float v2 = fmaxf(acc[mf][nf][2] + b2.x, 0.f);
            float v3 = fmaxf(acc[mf][nf][3] + b2.y, 0.f);
            if (row0 < M)
                *(__half2*)(C + (size_t)row0 * H_DIM + col) = __floats2half2_rn(v0, v1);
            if (row0 + 8 < M)
                *(__half2*)(C + (size_t)(row0 + 8) * H_DIM + col) = __floats2half2_rn(v2, v3);
        }
    }
}

// ---------------------------------------------------------------------------
__global__ void final_kernel(const __half* __restrict__ Y,
                             const float* __restrict__ Wo,
                             const float* __restrict__ bo,
                             float* __restrict__ out, int N) {
    int warp = (int)(((long long)blockIdx.x * blockDim.x + threadIdx.x) >> 5);
    int lane = threadIdx.x & 31;
    if (warp >= N) return;
    const __half2* y0 = (const __half2*)(Y + (size_t)warp * H_DIM);
    const __half2* y1 = (const __half2*)(Y + (size_t)(warp + N) * H_DIM);
    const __half2* y2 = (const __half2*)(Y + (size_t)(warp + 2 * N) * H_DIM);
    float s0 = 0.f, s1 = 0.f;
#pragma unroll
    for (int c = lane; c < H_DIM / 2; c += 32) {
        float2 a = __half22float2(y0[c]);
        float2 b = __half22float2(y1[c]);
        float2 d = __half22float2(y2[c]);
        float vx = a.x + b.x + d.x;
        float vy = a.y + b.y + d.y;
        s0 += vx * __ldg(&Wo[(2 * c) * 2 + 0]) + vy * __ldg(&Wo[(2 * c + 1) * 2 + 0]);
        s1 += vx * __ldg(&Wo[(2 * c) * 2 + 1]) + vy * __ldg(&Wo[(2 * c + 1) * 2 + 1]);
    }
#pragma unroll
    for (int off = 16; off; off >>= 1) {
        s0 += __shfl_down_sync(0xFFFFFFFFu, s0, off);
        s1 += __shfl_down_sync(0xFFFFFFFFu, s1, off);
    }
    if (lane == 0) {
        out[(size_t)warp * 2 + 0] = s0 + __ldg(&bo[0]);
        out[(size_t)warp * 2 + 1] = s1 + __ldg(&bo[1]);
    }
}

// ---------------------------------------------------------------------------
extern "C" void kernel_launch(void* const* d_in, const int* in_sizes, int n_in,
                              void* d_out, int out_size) {
    const float* h   = (const float*)d_in[0];
    const void*  idx = d_in[1];
    const float* W1  = (const float*)d_in[2];
    const float* b1  = (const float*)d_in[3];
    const float* W2  = (const float*)d_in[4];
    const float* b2  = (const float*)d_in[5];
    const float* W3  = (const float*)d_in[6];
    const float* b3  = (const float*)d_in[7];
    const float* Wo  = (const float*)d_in[8];
    const float* bo  = (const float*)d_in[9];
    float* out = (float*)d_out;

    int N   = in_sizes[1] / 4;
    int n_h = in_sizes[0] / F_DIM;
    int M   = 3 * N;

    __half* Y0 = nullptr; __half* Y1 = nullptr; __half* wt = nullptr;
    cudaGetSymbolAddress((void**)&Y0, g_Y0);
    cudaGetSymbolAddress((void**)&Y1, g_Y1);
    cudaGetSymbolAddress((void**)&wt, g_Wt16);
    __half* Wt1 = wt;
    __half* Wt2 = wt + H_DIM * H_DIM;
    __half* Wt3 = wt + 2 * H_DIM * H_DIM;

    detect_idx_kernel<<<1, 256>>>((const long long*)idx, n_h);

    int h4 = in_sizes[0] / 4;
    convert_h_kernel<<<(h4 + 255) / 256, 256>>>(h, h4);

    dim3 tb(32, 8), tg(16, 16);
    transpose512h_kernel<<<tg, tb>>>(W1, Wt1);
    transpose512h_kernel<<<tg, tb>>>(W2, Wt2);
    transpose512h_kernel<<<tg, tb>>>(W3, Wt3);

    int mtiles = (M + 127) / 128;
    dim3 ggrid(mtiles, H_DIM / 128);
    gemm_h_kernel<<<ggrid, 256>>>(nullptr, idx, Wt1, b1, Y0, M, N, 1);
    gemm_h_kernel<<<ggrid, 256>>>(Y0, nullptr, Wt2, b2, Y1, M, N, 0);
    gemm_h_kernel<<<ggrid, 256>>>(Y1, nullptr, Wt3, b3, Y0, M, N, 0);

    int fblocks = (N + 7) / 8;
    final_kernel<<<fblocks, 256>>>(Y0, Wo, bo, out, N);
}

// round 5
// speedup vs baseline: 6.2384x; 1.0339x over previous
#include <cuda_runtime.h>
#include <cuda_fp16.h>
#include <cstdint>

// ---------------------------------------------------------------------------
// JanossyPoolingImproper — Round 5: fp16 mma.sync, CTA 128x256, 512 threads,
// 3-stage cp.async pipeline, ntile-fastest grid for A L2 reuse.
// detect idx dtype -> h:f32->f16 -> W transpose->f16 ->
//   GEMM1 (gather fused) -> GEMM2 -> GEMM3 -> Janossy-sum + 512->2 proj.
// ---------------------------------------------------------------------------

#define H_DIM 512
#define F_DIM 128
#define MAX_N 100000
#define MAX_M (3 * MAX_N)
#define MAX_NH 50000

#define KC 32                      // K per stage
#define NSTAGE (H_DIM / KC)        // 16
#define ROWB 80                    // bytes per SMEM row: 64 data + 16 pad
#define A_TILE (128 * ROWB)        // 10240
#define B_TILE (256 * ROWB)        // 20480
#define SMEM_BYTES (3 * A_TILE + 3 * B_TILE)   // 92160

__constant__ int c_perms[3][4] = {{0,1,2,3},{2,1,3,0},{3,1,0,2}};

__device__ __half g_Y0[(size_t)MAX_M * H_DIM];
__device__ __half g_Y1[(size_t)MAX_M * H_DIM];
__device__ __half g_h16[(size_t)MAX_NH * F_DIM];
__device__ __half g_Wt16[3][H_DIM * H_DIM];
__device__ int    g_idx64_flag;

// ---------------------------- helpers -------------------------------------
__device__ __forceinline__ uint32_t smem_u32(const void* p) {
    uint32_t a;
    asm("{ .reg .u64 t; cvta.to.shared.u64 t, %1; cvt.u32.u64 %0, t; }" : "=r"(a) : "l"(p));
    return a;
}
__device__ __forceinline__ void cp16(uint32_t dst, const void* src, bool pred) {
    int bytes = pred ? 16 : 0;
    asm volatile("cp.async.ca.shared.global [%0], [%1], 16, %2;"
                 :: "r"(dst), "l"(src), "r"(bytes) : "memory");
}
__device__ __forceinline__ void cp_commit() {
    asm volatile("cp.async.commit_group;" ::: "memory");
}
template <int N>
__device__ __forceinline__ void cp_wait() {
    asm volatile("cp.async.wait_group %0;" :: "n"(N) : "memory");
}
__device__ __forceinline__ void ldm_x4(uint32_t* r, uint32_t addr) {
    asm volatile("ldmatrix.sync.aligned.m8n8.x4.shared.b16 {%0,%1,%2,%3}, [%4];"
                 : "=r"(r[0]), "=r"(r[1]), "=r"(r[2]), "=r"(r[3]) : "r"(addr));
}
__device__ __forceinline__ void mma_fp16(float* c, const uint32_t* a, const uint32_t* b) {
    asm volatile(
        "mma.sync.aligned.m16n8k16.row.col.f32.f16.f16.f32 "
        "{%0,%1,%2,%3}, {%4,%5,%6,%7}, {%8,%9}, {%0,%1,%2,%3};"
        : "+f"(c[0]), "+f"(c[1]), "+f"(c[2]), "+f"(c[3])
        : "r"(a[0]), "r"(a[1]), "r"(a[2]), "r"(a[3]), "r"(b[0]), "r"(b[1]));
}

// ---------------------------------------------------------------------------
__global__ void detect_idx_kernel(const long long* __restrict__ idx64, int n_h) {
    long long v = idx64[threadIdx.x];
    int ok = (v >= 0 && v < (long long)n_h) ? 1 : 0;
    int all = __syncthreads_and(ok);
    if (threadIdx.x == 0) g_idx64_flag = all;
}

__global__ void convert_h_kernel(const float* __restrict__ h, int total4) {
    int tid = blockIdx.x * blockDim.x + threadIdx.x;
    if (tid >= total4) return;
    float4 v = ((const float4*)h)[tid];
    ((__half2*)g_h16)[tid * 2 + 0] = __floats2half2_rn(v.x, v.y);
    ((__half2*)g_h16)[tid * 2 + 1] = __floats2half2_rn(v.z, v.w);
}

__global__ void transpose512h_kernel(const float* __restrict__ W, __half* __restrict__ Wt) {
    __shared__ float t[32][33];
    int x = blockIdx.x * 32 + threadIdx.x;
    int y0 = blockIdx.y * 32;
#pragma unroll
    for (int i = threadIdx.y; i < 32; i += 8)
        t[i][threadIdx.x] = W[(y0 + i) * H_DIM + x];
    __syncthreads();
    int nx = blockIdx.y * 32 + threadIdx.x;
    int ny0 = blockIdx.x * 32;
#pragma unroll
    for (int i = threadIdx.y; i < 32; i += 8)
        Wt[(ny0 + i) * H_DIM + nx] = __float2half_rn(t[threadIdx.x][i]);
}

// ---------------------------------------------------------------------------
// C[M,512] = relu(A @ Wt^T + bias). CTA 128(M) x 256(N), 512 threads,
// 16 warps as 2(M) x 8(N), warp tile 64x32 (4x4 m16n8k16), 3-stage cp.async.
// gather_mode=1: A rows from g_h16 via idx/perm (layer 1).
// ---------------------------------------------------------------------------
__global__ __launch_bounds__(512, 1) void gemm_h_kernel(
    const __half* __restrict__ Ah, const void* __restrict__ idx,
    const __half* __restrict__ Wt, const float* __restrict__ bias,
    __half* __restrict__ C, int M, int Nsamp, int gather_mode)
{
    extern __shared__ char smem[];
    uint32_t sA = smem_u32(smem);
    uint32_t sB = sA + 3 * A_TILE;

    int tid = threadIdx.x;
    int lane = tid & 31, wid = tid >> 5;
    int wm = wid >> 3, wn = wid & 7;
    int g = lane >> 2, t = lane & 3;
    int bn = blockIdx.x * 256;
    int bm = blockIdx.y * 128;

    // ---- per-thread loader state (fixed across stages) ----
    int a_row = tid >> 2;           // 0..127  (A: 128 rows x 4 chunks)
    int chunk = tid & 3;
    bool a_val = (bm + a_row) < M;
    int lp = 0;
    long long lnb[4];
    if (gather_mode) {
        int rc = a_val ? (bm + a_row) : 0;
        lp = (rc >= 2 * Nsamp) ? 2 : (rc >= Nsamp ? 1 : 0);
        int n = rc - lp * Nsamp;
        if (g_idx64_flag) {
#pragma unroll
            for (int s = 0; s < 4; s++)
                lnb[s] = ((const long long*)idx)[(long long)n * 4 + s];
        } else {
#pragma unroll
            for (int s = 0; s < 4; s++)
                lnb[s] = (long long)((const int*)idx)[n * 4 + s];
        }
    }

    auto load_stage = [&](int s) {
        int buf = s % 3;
        int k0 = s * KC;
        // A tile: one cp16 per thread
        {
            uint32_t dst = sA + buf * A_TILE + (uint32_t)(a_row * ROWB + chunk * 16);
            const __half* src;
            if (gather_mode) {
                int slot = c_perms[lp][s >> 2];
                src = g_h16 + lnb[slot] * F_DIM + (k0 & 127) + chunk * 8;
            } else {
                src = Ah + (size_t)(bm + a_row) * H_DIM + k0 + chunk * 8;
            }
            cp16(dst, src, a_val);
        }
        // B tile: 256 rows x 4 chunks = 1024 tasks, 2 per thread
#pragma unroll
        for (int i = 0; i < 2; i++) {
            int row = (tid >> 2) + i * 128;
            uint32_t dst = sB + buf * B_TILE + (uint32_t)(row * ROWB + chunk * 16);
            const __half* src = Wt + (size_t)(bn + row) * H_DIM + k0 + chunk * 8;
            cp16(dst, src, true);
        }
        cp_commit();
    };

    float acc[4][4][4];
#pragma unroll
    for (int i = 0; i < 4; i++)
#pragma unroll
        for (int j = 0; j < 4; j++)
#pragma unroll
            for (int r = 0; r < 4; r++) acc[i][j][r] = 0.0f;

    // ldmatrix per-lane address components
    int a_row_off = (lane & 7) + ((lane >> 3) & 1) * 8;
    int a_col_off = (lane >> 4) * 8;
    int b_row_off = (lane & 7) + (lane >> 4) * 8;
    int b_col_off = ((lane >> 3) & 1) * 8;

    load_stage(0);
    load_stage(1);

    for (int s = 0; s < NSTAGE; s++) {
        cp_wait<1>();                 // stage s data resident
        __syncthreads();              // also: everyone done reading buf (s+2)%3
        if (s + 2 < NSTAGE) load_stage(s + 2);
        else                cp_commit();   // keep group arithmetic uniform

        uint32_t aT = sA + (s % 3) * A_TILE;
        uint32_t bT = sB + (s % 3) * B_TILE;
#pragma unroll
        for (int ks = 0; ks < 2; ks++) {
            int k = ks * 16;
            uint32_t af[4][4], bf[4][2];
#pragma unroll
            for (int mf = 0; mf < 4; mf++) {
                int row = wm * 64 + mf * 16 + a_row_off;
                ldm_x4(af[mf], aT + (uint32_t)(row * ROWB + (k + a_col_off) * 2));
            }
#pragma unroll
            for (int nfp = 0; nfp < 2; nfp++) {
                uint32_t r4[4];
                int row = wn * 32 + nfp * 16 + b_row_off;
                ldm_x4(r4, bT + (uint32_t)(row * ROWB + (k + b_col_off) * 2));
                bf[nfp * 2 + 0][0] = r4[0]; bf[nfp * 2 + 0][1] = r4[1];
                bf[nfp * 2 + 1][0] = r4[2]; bf[nfp * 2 + 1][1] = r4[3];
            }
#pragma unroll
            for (int mf = 0; mf < 4; mf++)
#pragma unroll
                for (int nf = 0; nf < 4; nf++)
                    mma_fp16(acc[mf][nf], af[mf], bf[nf]);
        }
    }

    // ---- epilogue: bias + relu -> fp16 ----
#pragma unroll
    for (int nf = 0; nf < 4; nf++) {
        int col = bn + wn * 32 + nf * 8 + 2 * t;
        float2 b2 = *(const float2*)(bias + col);
#pragma unroll
        for (int mf = 0; mf < 4; mf++) {
            int row0 = bm + wm * 64 + mf * 16 + g;
            float v0 = fmaxf(acc[mf][nf][0] + b2.x, 0.f);
            float v1 = fmaxf(acc[mf][nf][1] + b2.y, 0.f);
            float v2 = fmaxf(acc[mf][nf][2] + b2.x, 0.f);
            float v3 = fmaxf(acc[mf][nf][3] + b2.y, 0.f);
            if (row0 < M)
                *(__half2*)(C + (size_t)row0 * H_DIM + col) = __floats2half2_rn(v0, v1);
            if (row0 + 8 < M)
                *(__half2*)(C + (size_t)(row0 + 8) * H_DIM + col) = __floats2half2_rn(v2, v3);
        }
    }
}

// ---------------------------------------------------------------------------
__global__ void final_kernel(const __half* __restrict__ Y,
                             const float* __restrict__ Wo,
                             const float* __restrict__ bo,
                             float* __restrict__ out, int N) {
    int warp = (int)(((long long)blockIdx.x * blockDim.x + threadIdx.x) >> 5);
    int lane = threadIdx.x & 31;
    if (warp >= N) return;
    const __half2* y0 = (const __half2*)(Y + (size_t)warp * H_DIM);
    const __half2* y1 = (const __half2*)(Y + (size_t)(warp + N) * H_DIM);
    const __half2* y2 = (const __half2*)(Y + (size_t)(warp + 2 * N) * H_DIM);
    float s0 = 0.f, s1 = 0.f;
#pragma unroll
    for (int c = lane; c < H_DIM / 2; c += 32) {
        float2 a = __half22float2(y0[c]);
        float2 b = __half22float2(y1[c]);
        float2 d = __half22float2(y2[c]);
        float vx = a.x + b.x + d.x;
        float vy = a.y + b.y + d.y;
        s0 += vx * __ldg(&Wo[(2 * c) * 2 + 0]) + vy * __ldg(&Wo[(2 * c + 1) * 2 + 0]);
        s1 += vx * __ldg(&Wo[(2 * c) * 2 + 1]) + vy * __ldg(&Wo[(2 * c + 1) * 2 + 1]);
    }
#pragma unroll
    for (int off = 16; off; off >>= 1) {
        s0 += __shfl_down_sync(0xFFFFFFFFu, s0, off);
        s1 += __shfl_down_sync(0xFFFFFFFFu, s1, off);
    }
    if (lane == 0) {
        out[(size_t)warp * 2 + 0] = s0 + __ldg(&bo[0]);
        out[(size_t)warp * 2 + 1] = s1 + __ldg(&bo[1]);
    }
}

// ---------------------------------------------------------------------------
extern "C" void kernel_launch(void* const* d_in, const int* in_sizes, int n_in,
                              void* d_out, int out_size) {
    const float* h   = (const float*)d_in[0];
    const void*  idx = d_in[1];
    const float* W1  = (const float*)d_in[2];
    const float* b1  = (const float*)d_in[3];
    const float* W2  = (const float*)d_in[4];
    const float* b2  = (const float*)d_in[5];
    const float* W3  = (const float*)d_in[6];
    const float* b3  = (const float*)d_in[7];
    const float* Wo  = (const float*)d_in[8];
    const float* bo  = (const float*)d_in[9];
    float* out = (float*)d_out;

    int N   = in_sizes[1] / 4;
    int n_h = in_sizes[0] / F_DIM;
    int M   = 3 * N;

    __half* Y0 = nullptr; __half* Y1 = nullptr; __half* wt = nullptr;
    cudaGetSymbolAddress((void**)&Y0, g_Y0);
    cudaGetSymbolAddress((void**)&Y1, g_Y1);
    cudaGetSymbolAddress((void**)&wt, g_Wt16);
    __half* Wt1 = wt;
    __half* Wt2 = wt + H_DIM * H_DIM;
    __half* Wt3 = wt + 2 * H_DIM * H_DIM;

    cudaFuncSetAttribute(gemm_h_kernel,
                         cudaFuncAttributeMaxDynamicSharedMemorySize, SMEM_BYTES);

    detect_idx_kernel<<<1, 256>>>((const long long*)idx, n_h);

    int h4 = in_sizes[0] / 4;
    convert_h_kernel<<<(h4 + 255) / 256, 256>>>(h, h4);

    dim3 tb(32, 8), tg(16, 16);
    transpose512h_kernel<<<tg, tb>>>(W1, Wt1);
    transpose512h_kernel<<<tg, tb>>>(W2, Wt2);
    transpose512h_kernel<<<tg, tb>>>(W3, Wt3);

    int mtiles = (M + 127) / 128;
    dim3 ggrid(H_DIM / 256, mtiles);     // ntile fastest -> A tile L2 reuse
    gemm_h_kernel<<<ggrid, 512, SMEM_BYTES>>>(nullptr, idx, Wt1, b1, Y0, M, N, 1);
    gemm_h_kernel<<<ggrid, 512, SMEM_BYTES>>>(Y0, nullptr, Wt2, b2, Y1, M, N, 0);
    gemm_h_kernel<<<ggrid, 512, SMEM_BYTES>>>(Y1, nullptr, Wt3, b3, Y0, M, N, 0);

    int fblocks = (N + 7) / 8;
    final_kernel<<<fblocks, 256>>>(Y0, Wo, bo, out, N);
}

// round 6
// speedup vs baseline: 6.7829x; 1.0873x over previous
#include <cuda_runtime.h>
#include <cuda_fp16.h>
#include <cstdint>

// ---------------------------------------------------------------------------
// JanossyPoolingImproper — Round 6: exploit Janossy/layer-1 structure.
//   P[node][j] = h[node] @ W1_block_j   (GEMM: [50k,128] @ [128,2048], 6x fewer
//   MACs than the naive layer-1 GEMM), then layer-1 rows are gather+add:
//   Y0[p*N+n] = relu(sum_j P[idx[n,perm_p[j]]][j] + b1).
// Layers 2,3 stay fp16 mma.sync GEMMs (already at the HMMA issue floor).
// ---------------------------------------------------------------------------

#define H_DIM 512
#define F_DIM 128
#define MAX_N 100000
#define MAX_M (3 * MAX_N)
#define MAX_NH 50000
#define MAX_NH_PAD 50048          // 391 * 128

#define KC 32                      // K per stage
#define ROWB 80                    // bytes per SMEM row: 64 data + 16 pad
#define A_TILE (128 * ROWB)        // 10240
#define B_TILE (256 * ROWB)        // 20480
#define SMEM_BYTES (3 * A_TILE + 3 * B_TILE)   // 92160

__device__ __half g_Y0[(size_t)MAX_M * H_DIM];
__device__ __half g_Y1[(size_t)MAX_M * H_DIM];
__device__ __half g_h16[(size_t)MAX_NH * F_DIM];
__device__ __half g_P[(size_t)MAX_NH_PAD * 2048];   // [node][j][512]
__device__ __half g_Wt16[2][H_DIM * H_DIM];         // W2^T, W3^T
__device__ __half g_W1P[2048 * F_DIM];              // [j*512+n][k]
__device__ int    g_idx64_flag;

// slot tables: slot s = perm[p][j] for j = 0,2,3 (perm[p][1]==1 for all p)
__constant__ int c_s0[3] = {0, 2, 3};
__constant__ int c_s2[3] = {2, 3, 0};
__constant__ int c_s3[3] = {3, 0, 2};

// ---------------------------- helpers -------------------------------------
__device__ __forceinline__ uint32_t smem_u32(const void* p) {
    uint32_t a;
    asm("{ .reg .u64 t; cvta.to.shared.u64 t, %1; cvt.u32.u64 %0, t; }" : "=r"(a) : "l"(p));
    return a;
}
__device__ __forceinline__ void cp16(uint32_t dst, const void* src, bool pred) {
    int bytes = pred ? 16 : 0;
    asm volatile("cp.async.ca.shared.global [%0], [%1], 16, %2;"
                 :: "r"(dst), "l"(src), "r"(bytes) : "memory");
}
__device__ __forceinline__ void cp_commit() {
    asm volatile("cp.async.commit_group;" ::: "memory");
}
template <int N>
__device__ __forceinline__ void cp_wait() {
    asm volatile("cp.async.wait_group %0;" :: "n"(N) : "memory");
}
__device__ __forceinline__ void ldm_x4(uint32_t* r, uint32_t addr) {
    asm volatile("ldmatrix.sync.aligned.m8n8.x4.shared.b16 {%0,%1,%2,%3}, [%4];"
                 : "=r"(r[0]), "=r"(r[1]), "=r"(r[2]), "=r"(r[3]) : "r"(addr));
}
__device__ __forceinline__ void mma_fp16(float* c, const uint32_t* a, const uint32_t* b) {
    asm volatile(
        "mma.sync.aligned.m16n8k16.row.col.f32.f16.f16.f32 "
        "{%0,%1,%2,%3}, {%4,%5,%6,%7}, {%8,%9}, {%0,%1,%2,%3};"
        : "+f"(c[0]), "+f"(c[1]), "+f"(c[2]), "+f"(c[3])
        : "r"(a[0]), "r"(a[1]), "r"(a[2]), "r"(a[3]), "r"(b[0]), "r"(b[1]));
}
__device__ __forceinline__ void acc_uint4(float* acc, uint4 u) {
    float2 f;
    f = __half22float2(*reinterpret_cast<__half2*>(&u.x)); acc[0] += f.x; acc[1] += f.y;
    f = __half22float2(*reinterpret_cast<__half2*>(&u.y)); acc[2] += f.x; acc[3] += f.y;
    f = __half22float2(*reinterpret_cast<__half2*>(&u.z)); acc[4] += f.x; acc[5] += f.y;
    f = __half22float2(*reinterpret_cast<__half2*>(&u.w)); acc[6] += f.x; acc[7] += f.y;
}
__device__ __forceinline__ void set_uint4(float* acc, uint4 u) {
    float2 f;
    f = __half22float2(*reinterpret_cast<__half2*>(&u.x)); acc[0] = f.x; acc[1] = f.y;
    f = __half22float2(*reinterpret_cast<__half2*>(&u.y)); acc[2] = f.x; acc[3] = f.y;
    f = __half22float2(*reinterpret_cast<__half2*>(&u.z)); acc[4] = f.x; acc[5] = f.y;
    f = __half22float2(*reinterpret_cast<__half2*>(&u.w)); acc[6] = f.x; acc[7] = f.y;
}

// ---------------------------------------------------------------------------
__global__ void detect_idx_kernel(const long long* __restrict__ idx64, int n_h) {
    long long v = idx64[threadIdx.x];
    int ok = (v >= 0 && v < (long long)n_h) ? 1 : 0;
    int all = __syncthreads_and(ok);
    if (threadIdx.x == 0) g_idx64_flag = all;
}

__global__ void convert_h_kernel(const float* __restrict__ h, int total4) {
    int tid = blockIdx.x * blockDim.x + threadIdx.x;
    if (tid >= total4) return;
    float4 v = ((const float4*)h)[tid];
    ((__half2*)g_h16)[tid * 2 + 0] = __floats2half2_rn(v.x, v.y);
    ((__half2*)g_h16)[tid * 2 + 1] = __floats2half2_rn(v.z, v.w);
}

// W[k][n] (512x512) -> Wt16[n][k] fp16
__global__ void transpose512h_kernel(const float* __restrict__ W, __half* __restrict__ Wt) {
    __shared__ float t[32][33];
    int x = blockIdx.x * 32 + threadIdx.x;
    int y0 = blockIdx.y * 32;
#pragma unroll
    for (int i = threadIdx.y; i < 32; i += 8)
        t[i][threadIdx.x] = W[(y0 + i) * H_DIM + x];
    __syncthreads();
    int nx = blockIdx.y * 32 + threadIdx.x;
    int ny0 = blockIdx.x * 32;
#pragma unroll
    for (int i = threadIdx.y; i < 32; i += 8)
        Wt[(ny0 + i) * H_DIM + nx] = __float2half_rn(t[threadIdx.x][i]);
}

// W1[k'][n] (512x512, k' = j*128+kk) -> W1P[j*512+n][kk] fp16 (K-major, stride 128)
__global__ void transposeW1_kernel(const float* __restrict__ W1, __half* __restrict__ W1P) {
    __shared__ float t[32][33];
    int x = blockIdx.x * 32 + threadIdx.x;     // n
    int y0 = blockIdx.y * 32;                  // k'
#pragma unroll
    for (int i = threadIdx.y; i < 32; i += 8)
        t[i][threadIdx.x] = W1[(y0 + i) * H_DIM + x];
    __syncthreads();
    int kprime = blockIdx.y * 32 + threadIdx.x;
    int j = kprime >> 7, kk = kprime & 127;
    int n0 = blockIdx.x * 32;
#pragma unroll
    for (int i = threadIdx.y; i < 32; i += 8) {
        int n = n0 + i;
        W1P[(size_t)(j * 512 + n) * F_DIM + kk] = __float2half_rn(t[threadIdx.x][i]);
    }
}

// ---------------------------------------------------------------------------
// C[M, c_stride slice] = (relu?)(A[M,K] @ Wt^T + bias?). CTA 128(M) x 256(N),
// 512 threads, 16 warps as 2(M) x 8(N), warp tile 64x32, 3-stage cp.async.
// Wt rows are K-major with stride K. C row stride = c_stride.
// ---------------------------------------------------------------------------
__global__ __launch_bounds__(512, 1) void gemm_h_kernel(
    const __half* __restrict__ Ah, const __half* __restrict__ Wt,
    const float* __restrict__ bias, __half* __restrict__ C,
    int M, int K, int c_stride, int relu_mode)
{
    extern __shared__ char smem[];
    uint32_t sA = smem_u32(smem);
    uint32_t sB = sA + 3 * A_TILE;
    int nstages = K / KC;

    int tid = threadIdx.x;
    int lane = tid & 31, wid = tid >> 5;
    int wm = wid >> 3, wn = wid & 7;
    int g = lane >> 2, t = lane & 3;
    int bn = blockIdx.x * 256;
    int bm = blockIdx.y * 128;

    int a_row = tid >> 2;
    int chunk = tid & 3;
    bool a_val = (bm + a_row) < M;

    auto load_stage = [&](int s) {
        int buf = s % 3;
        int k0 = s * KC;
        {
            uint32_t dst = sA + buf * A_TILE + (uint32_t)(a_row * ROWB + chunk * 16);
            const __half* src = Ah + (size_t)(bm + a_row) * K + k0 + chunk * 8;
            cp16(dst, src, a_val);
        }
#pragma unroll
        for (int i = 0; i < 2; i++) {
            int row = (tid >> 2) + i * 128;
            uint32_t dst = sB + buf * B_TILE + (uint32_t)(row * ROWB + chunk * 16);
            const __half* src = Wt + (size_t)(bn + row) * K + k0 + chunk * 8;
            cp16(dst, src, true);
        }
        cp_commit();
    };

    float acc[4][4][4];
#pragma unroll
    for (int i = 0; i < 4; i++)
#pragma unroll
        for (int j = 0; j < 4; j++)
#pragma unroll
            for (int r = 0; r < 4; r++) acc[i][j][r] = 0.0f;

    int a_row_off = (lane & 7) + ((lane >> 3) & 1) * 8;
    int a_col_off = (lane >> 4) * 8;
    int b_row_off = (lane & 7) + (lane >> 4) * 8;
    int b_col_off = ((lane >> 3) & 1) * 8;

    load_stage(0);
    load_stage(1);

    for (int s = 0; s < nstages; s++) {
        cp_wait<1>();
        __syncthreads();
        if (s + 2 < nstages) load_stage(s + 2);
        else                 cp_commit();

        uint32_t aT = sA + (s % 3) * A_TILE;
        uint32_t bT = sB + (s % 3) * B_TILE;
#pragma unroll
        for (int ks = 0; ks < 2; ks++) {
            int k = ks * 16;
            uint32_t af[4][4], bf[4][2];
#pragma unroll
            for (int mf = 0; mf < 4; mf++) {
                int row = wm * 64 + mf * 16 + a_row_off;
                ldm_x4(af[mf], aT + (uint32_t)(row * ROWB + (k + a_col_off) * 2));
            }
#pragma unroll
            for (int nfp = 0; nfp < 2; nfp++) {
                uint32_t r4[4];
                int row = wn * 32 + nfp * 16 + b_row_off;
                ldm_x4(r4, bT + (uint32_t)(row * ROWB + (k + b_col_off) * 2));
                bf[nfp * 2 + 0][0] = r4[0]; bf[nfp * 2 + 0][1] = r4[1];
                bf[nfp * 2 + 1][0] = r4[2]; bf[nfp * 2 + 1][1] = r4[3];
            }
#pragma unroll
            for (int mf = 0; mf < 4; mf++)
#pragma unroll
                for (int nf = 0; nf < 4; nf++)
                    mma_fp16(acc[mf][nf], af[mf], bf[nf]);
        }
    }

#pragma unroll
    for (int nf = 0; nf < 4; nf++) {
        int col = bn + wn * 32 + nf * 8 + 2 * t;
        float2 b2 = bias ? *(const float2*)(bias + col) : make_float2(0.f, 0.f);
#pragma unroll
        for (int mf = 0; mf < 4; mf++) {
            int row0 = bm + wm * 64 + mf * 16 + g;
            float v0 = acc[mf][nf][0] + b2.x;
            float v1 = acc[mf][nf][1] + b2.y;
            float v2 = acc[mf][nf][2] + b2.x;
            float v3 = acc[mf][nf][3] + b2.y;
            if (relu_mode) {
                v0 = fmaxf(v0, 0.f); v1 = fmaxf(v1, 0.f);
                v2 = fmaxf(v2, 0.f); v3 = fmaxf(v3, 0.f);
            }
            if (row0 < M)
                *(__half2*)(C + (size_t)row0 * c_stride + col) = __floats2half2_rn(v0, v1);
            if (row0 + 8 < M)
                *(__half2*)(C + (size_t)(row0 + 8) * c_stride + col) = __floats2half2_rn(v2, v3);
        }
    }
}

// ---------------------------------------------------------------------------
// Layer-1 assembly: Y0[p*N+n] = relu(sum_j P[idx[n,perm_p[j]]][j] + b1).
// One warp per sample n; the j==1 term (slot 1 in every perm) is loaded once.
// Lane handles cols [lane*8, lane*8+8) and [256+lane*8, ...+8).
// ---------------------------------------------------------------------------
__global__ void assemble_kernel(const void* __restrict__ idx,
                                const float* __restrict__ b1,
                                __half* __restrict__ Y, int N) {
    int warp = (int)(((long long)blockIdx.x * blockDim.x + threadIdx.x) >> 5);
    int lane = threadIdx.x & 31;
    if (warp >= N) return;
    int n = warp;

    long long node[4];
    if (g_idx64_flag) {
#pragma unroll
        for (int s = 0; s < 4; s++) node[s] = ((const long long*)idx)[(long long)n * 4 + s];
    } else {
#pragma unroll
        for (int s = 0; s < 4; s++) node[s] = (long long)((const int*)idx)[n * 4 + s];
    }

    float bs[16];
#pragma unroll
    for (int i = 0; i < 8; i++) bs[i] = __ldg(&b1[lane * 8 + i]);
#pragma unroll
    for (int i = 0; i < 8; i++) bs[8 + i] = __ldg(&b1[256 + lane * 8 + i]);

    // shared j==1 term
    const uint4* p1 = (const uint4*)(g_P + node[1] * 2048 + 512) + lane;
    uint4 c1a = __ldg(p1);
    uint4 c1b = __ldg(p1 + 32);

#pragma unroll
    for (int p = 0; p < 3; p++) {
        float acc[16];
        set_uint4(acc, c1a);
        set_uint4(acc + 8, c1b);

        int s0 = c_s0[p], s2 = c_s2[p], s3 = c_s3[p];
        const uint4* r0 = (const uint4*)(g_P + node[s0] * 2048 + 0)    + lane;
        const uint4* r2 = (const uint4*)(g_P + node[s2] * 2048 + 1024) + lane;
        const uint4* r3 = (const uint4*)(g_P + node[s3] * 2048 + 1536) + lane;
        acc_uint4(acc,     __ldg(r0)); acc_uint4(acc + 8, __ldg(r0 + 32));
        acc_uint4(acc,     __ldg(r2)); acc_uint4(acc + 8, __ldg(r2 + 32));
        acc_uint4(acc,     __ldg(r3)); acc_uint4(acc + 8, __ldg(r3 + 32));

        __half* dst = Y + (size_t)(p * N + n) * H_DIM;
        uint4 o;
        __half2* oh = (__half2*)&o;
#pragma unroll
        for (int i = 0; i < 4; i++)
            oh[i] = __floats2half2_rn(fmaxf(acc[2*i] + bs[2*i], 0.f),
                                      fmaxf(acc[2*i+1] + bs[2*i+1], 0.f));
        *((uint4*)(dst + lane * 8)) = o;
#pragma unroll
        for (int i = 0; i < 4; i++)
            oh[i] = __floats2half2_rn(fmaxf(acc[8+2*i] + bs[8+2*i], 0.f),
                                      fmaxf(acc[8+2*i+1] + bs[8+2*i+1], 0.f));
        *((uint4*)(dst + 256 + lane * 8)) = o;
    }
}

// ---------------------------------------------------------------------------
__global__ void final_kernel(const __half* __restrict__ Y,
                             const float* __restrict__ Wo,
                             const float* __restrict__ bo,
                             float* __restrict__ out, int N) {
    int warp = (int)(((long long)blockIdx.x * blockDim.x + threadIdx.x) >> 5);
    int lane = threadIdx.x & 31;
    if (warp >= N) return;
    const __half2* y0 = (const __half2*)(Y + (size_t)warp * H_DIM);
    const __half2* y1 = (const __half2*)(Y + (size_t)(warp + N) * H_DIM);
    const __half2* y2 = (const __half2*)(Y + (size_t)(warp + 2 * N) * H_DIM);
    float s0 = 0.f, s1 = 0.f;
#pragma unroll
    for (int c = lane; c < H_DIM / 2; c += 32) {
        float2 a = __half22float2(y0[c]);
        float2 b = __half22float2(y1[c]);
        float2 d = __half22float2(y2[c]);
        float vx = a.x + b.x + d.x;
        float vy = a.y + b.y + d.y;
        s0 += vx * __ldg(&Wo[(2 * c) * 2 + 0]) + vy * __ldg(&Wo[(2 * c + 1) * 2 + 0]);
        s1 += vx * __ldg(&Wo[(2 * c) * 2 + 1]) + vy * __ldg(&Wo[(2 * c + 1) * 2 + 1]);
    }
#pragma unroll
    for (int off = 16; off; off >>= 1) {
        s0 += __shfl_down_sync(0xFFFFFFFFu, s0, off);
        s1 += __shfl_down_sync(0xFFFFFFFFu, s1, off);
    }
    if (lane == 0) {
        out[(size_t)warp * 2 + 0] = s0 + __ldg(&bo[0]);
        out[(size_t)warp * 2 + 1] = s1 + __ldg(&bo[1]);
    }
}

// ---------------------------------------------------------------------------
extern "C" void kernel_launch(void* const* d_in, const int* in_sizes, int n_in,
                              void* d_out, int out_size) {
    const float* h   = (const float*)d_in[0];
    const void*  idx = d_in[1];
    const float* W1  = (const float*)d_in[2];
    const float* b1  = (const float*)d_in[3];
    const float* W2  = (const float*)d_in[4];
    const float* b2  = (const float*)d_in[5];
    const float* W3  = (const float*)d_in[6];
    const float* b3  = (const float*)d_in[7];
    const float* Wo  = (const float*)d_in[8];
    const float* bo  = (const float*)d_in[9];
    float* out = (float*)d_out;

    int N   = in_sizes[1] / 4;
    int n_h = in_sizes[0] / F_DIM;
    int M   = 3 * N;

    __half *Y0, *Y1, *h16, *P, *wt, *w1p;
    cudaGetSymbolAddress((void**)&Y0, g_Y0);
    cudaGetSymbolAddress((void**)&Y1, g_Y1);
    cudaGetSymbolAddress((void**)&h16, g_h16);
    cudaGetSymbolAddress((void**)&P, g_P);
    cudaGetSymbolAddress((void**)&wt, g_Wt16);
    cudaGetSymbolAddress((void**)&w1p, g_W1P);
    __half* Wt2 = wt;
    __half* Wt3 = wt + H_DIM * H_DIM;

    cudaFuncSetAttribute(gemm_h_kernel,
                         cudaFuncAttributeMaxDynamicSharedMemorySize, SMEM_BYTES);

    detect_idx_kernel<<<1, 256>>>((const long long*)idx, n_h);

    int h4 = in_sizes[0] / 4;
    convert_h_kernel<<<(h4 + 255) / 256, 256>>>(h, h4);

    dim3 tb(32, 8), tg(16, 16);
    transposeW1_kernel<<<tg, tb>>>(W1, w1p);
    transpose512h_kernel<<<tg, tb>>>(W2, Wt2);
    transpose512h_kernel<<<tg, tb>>>(W3, Wt3);

    // P = h16 @ W1P^T : [n_h,128] x [2048,128] -> [n_h,2048]
    dim3 pgrid(2048 / 256, (n_h + 127) / 128);
    gemm_h_kernel<<<pgrid, 512, SMEM_BYTES>>>(h16, w1p, nullptr, P, n_h, F_DIM, 2048, 0);

    // layer-1 assembly -> Y0
    int ablocks = (N + 7) / 8;
    assemble_kernel<<<ablocks, 256>>>(idx, b1, Y0, N);

    // layers 2,3
    int mtiles = (M + 127) / 128;
    dim3 ggrid(H_DIM / 256, mtiles);
    gemm_h_kernel<<<ggrid, 512, SMEM_BYTES>>>(Y0, Wt2, b2, Y1, M, H_DIM, H_DIM, 1);
    gemm_h_kernel<<<ggrid, 512, SMEM_BYTES>>>(Y1, Wt3, b3, Y0, M, H_DIM, H_DIM, 1);

    int fblocks = (N + 7) / 8;
    final_kernel<<<fblocks, 256>>>(Y0, Wo, bo, out, N);
}

// round 7
// speedup vs baseline: 7.0555x; 1.0402x over previous
#include <cuda_runtime.h>
#include <cuda_fp16.h>
#include <cstdint>

// ---------------------------------------------------------------------------
// JanossyPoolingImproper — Round 7: fuse glue kernels into the GEMMs.
//   P[node][j] = h[node] @ W1_block_j          (small GEMM, [50k,128]x[128,2048])
//   GEMM2: A-tile produced on the fly: A[p*N+n][c] = relu(sum_j P[idx[n,perm_p[j]]][j][c] + b1[c])
//   GEMM3: epilogue projects relu(acc+b3) @ Wo directly into out via atomics.
// ---------------------------------------------------------------------------

#define H_DIM 512
#define F_DIM 128
#define MAX_N 100000
#define MAX_M (3 * MAX_N)
#define MAX_NH 50000
#define MAX_NH_PAD 50048

#define KC 32
#define ROWB 80
#define A_TILE (128 * ROWB)          // 10240
#define B_TILE (256 * ROWB)          // 20480
#define SM_B1OFF (3 * A_TILE + 3 * B_TILE)      // 92160
#define SM_POOFF (SM_B1OFF + 2048)              // 94208
#define SMEM_TOTAL (SM_POOFF + 1024)            // 95232

__constant__ int c_perms[3][4] = {{0,1,2,3},{2,1,3,0},{3,1,0,2}};

__device__ __half g_Y0[(size_t)MAX_M * H_DIM];
__device__ __half g_h16[(size_t)MAX_NH * F_DIM];
__device__ __half g_P[(size_t)MAX_NH_PAD * 2048];   // [node][j][512]
__device__ __half g_Wt16[2][H_DIM * H_DIM];         // W2^T, W3^T
__device__ __half g_W1P[2048 * F_DIM];              // [j*512+n][k]
__device__ int    g_idx64_flag;

// ---------------------------- helpers -------------------------------------
__device__ __forceinline__ uint32_t smem_u32(const void* p) {
    uint32_t a;
    asm("{ .reg .u64 t; cvta.to.shared.u64 t, %1; cvt.u32.u64 %0, t; }" : "=r"(a) : "l"(p));
    return a;
}
__device__ __forceinline__ void cp16(uint32_t dst, const void* src, bool pred) {
    int bytes = pred ? 16 : 0;
    asm volatile("cp.async.ca.shared.global [%0], [%1], 16, %2;"
                 :: "r"(dst), "l"(src), "r"(bytes) : "memory");
}
__device__ __forceinline__ void cp_commit() {
    asm volatile("cp.async.commit_group;" ::: "memory");
}
template <int N>
__device__ __forceinline__ void cp_wait() {
    asm volatile("cp.async.wait_group %0;" :: "n"(N) : "memory");
}
__device__ __forceinline__ void ldm_x4(uint32_t* r, uint32_t addr) {
    asm volatile("ldmatrix.sync.aligned.m8n8.x4.shared.b16 {%0,%1,%2,%3}, [%4];"
                 : "=r"(r[0]), "=r"(r[1]), "=r"(r[2]), "=r"(r[3]) : "r"(addr));
}
__device__ __forceinline__ void mma_fp16(float* c, const uint32_t* a, const uint32_t* b) {
    asm volatile(
        "mma.sync.aligned.m16n8k16.row.col.f32.f16.f16.f32 "
        "{%0,%1,%2,%3}, {%4,%5,%6,%7}, {%8,%9}, {%0,%1,%2,%3};"
        : "+f"(c[0]), "+f"(c[1]), "+f"(c[2]), "+f"(c[3])
        : "r"(a[0]), "r"(a[1]), "r"(a[2]), "r"(a[3]), "r"(b[0]), "r"(b[1]));
}

// ---------------------------------------------------------------------------
__global__ void detect_idx_kernel(const long long* __restrict__ idx64, int n_h) {
    long long v = idx64[threadIdx.x];
    int ok = (v >= 0 && v < (long long)n_h) ? 1 : 0;
    int all = __syncthreads_and(ok);
    if (threadIdx.x == 0) g_idx64_flag = all;
}

__global__ void convert_h_kernel(const float* __restrict__ h, int total4) {
    int tid = blockIdx.x * blockDim.x + threadIdx.x;
    if (tid >= total4) return;
    float4 v = ((const float4*)h)[tid];
    ((__half2*)g_h16)[tid * 2 + 0] = __floats2half2_rn(v.x, v.y);
    ((__half2*)g_h16)[tid * 2 + 1] = __floats2half2_rn(v.z, v.w);
}

__global__ void transpose512h_kernel(const float* __restrict__ W, __half* __restrict__ Wt) {
    __shared__ float t[32][33];
    int x = blockIdx.x * 32 + threadIdx.x;
    int y0 = blockIdx.y * 32;
#pragma unroll
    for (int i = threadIdx.y; i < 32; i += 8)
        t[i][threadIdx.x] = W[(y0 + i) * H_DIM + x];
    __syncthreads();
    int nx = blockIdx.y * 32 + threadIdx.x;
    int ny0 = blockIdx.x * 32;
#pragma unroll
    for (int i = threadIdx.y; i < 32; i += 8)
        Wt[(ny0 + i) * H_DIM + nx] = __float2half_rn(t[threadIdx.x][i]);
}

// W1[k'][n] -> W1P[j*512+n][kk]  (k' = j*128+kk), K-major stride 128
__global__ void transposeW1_kernel(const float* __restrict__ W1, __half* __restrict__ W1P) {
    __shared__ float t[32][33];
    int x = blockIdx.x * 32 + threadIdx.x;
    int y0 = blockIdx.y * 32;
#pragma unroll
    for (int i = threadIdx.y; i < 32; i += 8)
        t[i][threadIdx.x] = W1[(y0 + i) * H_DIM + x];
    __syncthreads();
    int kprime = blockIdx.y * 32 + threadIdx.x;
    int j = kprime >> 7, kk = kprime & 127;
    int n0 = blockIdx.x * 32;
#pragma unroll
    for (int i = threadIdx.y; i < 32; i += 8) {
        int n = n0 + i;
        W1P[(size_t)(j * 512 + n) * F_DIM + kk] = __float2half_rn(t[threadIdx.x][i]);
    }
}

__global__ void init_out_kernel(const float* __restrict__ bo, float* __restrict__ out, int N) {
    int i = blockIdx.x * blockDim.x + threadIdx.x;
    if (i < N) {
        out[(size_t)i * 2 + 0] = __ldg(&bo[0]);
        out[(size_t)i * 2 + 1] = __ldg(&bo[1]);
    }
}

// ---------------------------------------------------------------------------
// Unified GEMM: C = (relu)(A[M,K] @ Wt^T + bias).  CTA 128x256, 512 thr,
// 16 warps 2(M)x8(N), warp tile 64x32, cp.async pipeline for B (+A if !GATHER).
// GATHER: A row (p*N+n) built on the fly from 4 gathered P segments (+b1,relu).
// PROJ:   no C store; epilogue computes relu(acc+bias) @ Wo -> atomicAdd(out).
// ---------------------------------------------------------------------------
template <int GATHER, int PROJ>
__global__ __launch_bounds__(512, 1) void gemm_fused_kernel(
    const __half* __restrict__ Ah, const __half* __restrict__ Wt,
    const float* __restrict__ bias, __half* __restrict__ C,
    int M, int K, int c_stride,
    const void* __restrict__ idx, const float* __restrict__ b1, int Nsamp,
    const float* __restrict__ Wo, float* __restrict__ out)
{
    extern __shared__ char smem[];
    uint32_t sA = smem_u32(smem);
    uint32_t sB = sA + 3 * A_TILE;
    float* b1s = (float*)(smem + SM_B1OFF);
    float* po  = (float*)(smem + SM_POOFF);
    int nstages = K / KC;

    int tid = threadIdx.x;
    int lane = tid & 31, wid = tid >> 5;
    int wm = wid >> 3, wn = wid & 7;
    int g = lane >> 2, t = lane & 3;
    int bn = blockIdx.x * 256;
    int bm = blockIdx.y * 128;

    int a_row = tid >> 2;
    int chunk = tid & 3;
    bool a_val = (bm + a_row) < M;

    // -------- gather-mode A producer state --------
    const __half* seg[4];
    uint4 areg[4];
    if (GATHER) {
        b1s[tid & 511] = b1[tid & 511];
        int row = a_val ? (bm + a_row) : 0;
        int p = (row >= 2 * Nsamp) ? 2 : (row >= Nsamp ? 1 : 0);
        int n = row - p * Nsamp;
        long long node[4];
        if (g_idx64_flag) {
#pragma unroll
            for (int s = 0; s < 4; s++) node[s] = ((const long long*)idx)[(long long)n * 4 + s];
        } else {
#pragma unroll
            for (int s = 0; s < 4; s++) node[s] = (long long)((const int*)idx)[n * 4 + s];
        }
#pragma unroll
        for (int j = 0; j < 4; j++)
            seg[j] = g_P + node[c_perms[p][j]] * 2048 + j * 512 + chunk * 8;
        // prefetch stage 0
#pragma unroll
        for (int j = 0; j < 4; j++) areg[j] = __ldg((const uint4*)(seg[j]));
    }

    auto load_B = [&](int s) {
        int buf = s % 3;
        int k0 = s * KC;
#pragma unroll
        for (int i = 0; i < 2; i++) {
            int row = (tid >> 2) + i * 128;
            uint32_t dst = sB + buf * B_TILE + (uint32_t)(row * ROWB + chunk * 16);
            cp16(dst, Wt + (size_t)(bn + row) * K + k0 + chunk * 8, true);
        }
    };
    auto load_A_cp = [&](int s) {
        int buf = s % 3;
        int k0 = s * KC;
        uint32_t dst = sA + buf * A_TILE + (uint32_t)(a_row * ROWB + chunk * 16);
        cp16(dst, Ah + (size_t)(bm + a_row) * K + k0 + chunk * 8, a_val);
    };

    // prologue
    if (!GATHER) load_A_cp(0);
    load_B(0); cp_commit();
    if (!GATHER) load_A_cp(1);
    load_B(1); cp_commit();
    if (GATHER) __syncthreads();   // b1s visible

    float acc[4][4][4];
#pragma unroll
    for (int i = 0; i < 4; i++)
#pragma unroll
        for (int j = 0; j < 4; j++)
#pragma unroll
            for (int r = 0; r < 4; r++) acc[i][j][r] = 0.0f;

    int a_row_off = (lane & 7) + ((lane >> 3) & 1) * 8;
    int a_col_off = (lane >> 4) * 8;
    int b_row_off = (lane & 7) + (lane >> 4) * 8;
    int b_col_off = ((lane >> 3) & 1) * 8;

    for (int s = 0; s < nstages; s++) {
        cp_wait<1>();
        if (GATHER) {
            // combine prefetched segments -> A tile (buf s&1)
            int col0 = s * KC + chunk * 8;
            uint4 o;
            __half2* oh = (__half2*)&o;
#pragma unroll
            for (int i = 0; i < 4; i++) {
                float2 f0 = __half22float2(((const __half2*)&areg[0])[i]);
                float2 f1 = __half22float2(((const __half2*)&areg[1])[i]);
                float2 f2 = __half22float2(((const __half2*)&areg[2])[i]);
                float2 f3 = __half22float2(((const __half2*)&areg[3])[i]);
                float vx = f0.x + f1.x + f2.x + f3.x + b1s[col0 + 2 * i];
                float vy = f0.y + f1.y + f2.y + f3.y + b1s[col0 + 2 * i + 1];
                if (!a_val) { vx = 0.f; vy = 0.f; }
                oh[i] = __floats2half2_rn(fmaxf(vx, 0.f), fmaxf(vy, 0.f));
            }
            *(uint4*)(smem + (s & 1) * A_TILE + a_row * ROWB + chunk * 16) = o;
        }
        __syncthreads();
        if (GATHER && s + 1 < nstages) {
#pragma unroll
            for (int j = 0; j < 4; j++)
                areg[j] = __ldg((const uint4*)(seg[j] + (s + 1) * KC));
        }
        if (s + 2 < nstages) {
            if (!GATHER) load_A_cp(s + 2);
            load_B(s + 2);
            cp_commit();
        } else cp_commit();

        uint32_t aT = sA + (GATHER ? (s & 1) : (s % 3)) * A_TILE;
        uint32_t bT = sB + (s % 3) * B_TILE;
#pragma unroll
        for (int ks = 0; ks < 2; ks++) {
            int k = ks * 16;
            uint32_t af[4][4], bf[4][2];
#pragma unroll
            for (int mf = 0; mf < 4; mf++) {
                int row = wm * 64 + mf * 16 + a_row_off;
                ldm_x4(af[mf], aT + (uint32_t)(row * ROWB + (k + a_col_off) * 2));
            }
#pragma unroll
            for (int nfp = 0; nfp < 2; nfp++) {
                uint32_t r4[4];
                int row = wn * 32 + nfp * 16 + b_row_off;
                ldm_x4(r4, bT + (uint32_t)(row * ROWB + (k + b_col_off) * 2));
                bf[nfp * 2 + 0][0] = r4[0]; bf[nfp * 2 + 0][1] = r4[1];
                bf[nfp * 2 + 1][0] = r4[2]; bf[nfp * 2 + 1][1] = r4[3];
            }
#pragma unroll
            for (int mf = 0; mf < 4; mf++)
#pragma unroll
                for (int nf = 0; nf < 4; nf++)
                    mma_fp16(acc[mf][nf], af[mf], bf[nf]);
        }
    }

    if (PROJ) {
        // ---- projection epilogue: relu(acc + b3) @ Wo -> out (atomics) ----
        __syncthreads();
        if (tid < 256) po[tid] = 0.f;
        __syncthreads();
#pragma unroll
        for (int mf = 0; mf < 4; mf++) {
#pragma unroll
            for (int sub = 0; sub < 2; sub++) {
                float p0 = 0.f, p1 = 0.f;
#pragma unroll
                for (int nf = 0; nf < 4; nf++) {
                    int col = bn + wn * 32 + nf * 8 + 2 * t;
                    float2 b2 = *(const float2*)(bias + col);
                    float v0 = fmaxf(acc[mf][nf][sub * 2 + 0] + b2.x, 0.f);
                    float v1 = fmaxf(acc[mf][nf][sub * 2 + 1] + b2.y, 0.f);
                    p0 += v0 * __ldg(&Wo[col * 2 + 0]) + v1 * __ldg(&Wo[(col + 1) * 2 + 0]);
                    p1 += v0 * __ldg(&Wo[col * 2 + 1]) + v1 * __ldg(&Wo[(col + 1) * 2 + 1]);
                }
                p0 += __shfl_xor_sync(0xFFFFFFFFu, p0, 1);
                p0 += __shfl_xor_sync(0xFFFFFFFFu, p0, 2);
                p1 += __shfl_xor_sync(0xFFFFFFFFu, p1, 1);
                p1 += __shfl_xor_sync(0xFFFFFFFFu, p1, 2);
                if (t == 0) {
                    int rloc = wm * 64 + mf * 16 + sub * 8 + g;
                    atomicAdd(&po[rloc * 2 + 0], p0);
                    atomicAdd(&po[rloc * 2 + 1], p1);
                }
            }
        }
        __syncthreads();
        if (tid < 256) {
            int rloc = tid >> 1, comp = tid & 1;
            int row = bm + rloc;
            if (row < M) {
                int p = (row >= 2 * Nsamp) ? 2 : (row >= Nsamp ? 1 : 0);
                int n = row - p * Nsamp;
                atomicAdd(&out[(size_t)n * 2 + comp], po[rloc * 2 + comp]);
            }
        }
    } else {
        // ---- standard epilogue: (bias?) + relu? -> fp16 C ----
#pragma unroll
        for (int nf = 0; nf < 4; nf++) {
            int col = bn + wn * 32 + nf * 8 + 2 * t;
            float2 b2 = bias ? *(const float2*)(bias + col) : make_float2(0.f, 0.f);
#pragma unroll
            for (int mf = 0; mf < 4; mf++) {
                int row0 = bm + wm * 64 + mf * 16 + g;
                float v0 = acc[mf][nf][0] + b2.x;
                float v1 = acc[mf][nf][1] + b2.y;
                float v2 = acc[mf][nf][2] + b2.x;
                float v3 = acc[mf][nf][3] + b2.y;
                if (bias) {   // layers with bias also have relu
                    v0 = fmaxf(v0, 0.f); v1 = fmaxf(v1, 0.f);
                    v2 = fmaxf(v2, 0.f); v3 = fmaxf(v3, 0.f);
                }
                if (row0 < M)
                    *(__half2*)(C + (size_t)row0 * c_stride + col) = __floats2half2_rn(v0, v1);
                if (row0 + 8 < M)
                    *(__half2*)(C + (size_t)(row0 + 8) * c_stride + col) = __floats2half2_rn(v2, v3);
            }
        }
    }
}

// ---------------------------------------------------------------------------
extern "C" void kernel_launch(void* const* d_in, const int* in_sizes, int n_in,
                              void* d_out, int out_size) {
    const float* h   = (const float*)d_in[0];
    const void*  idx = d_in[1];
    const float* W1  = (const float*)d_in[2];
    const float* b1  = (const float*)d_in[3];
    const float* W2  = (const float*)d_in[4];
    const float* b2  = (const float*)d_in[5];
    const float* W3  = (const float*)d_in[6];
    const float* b3  = (const float*)d_in[7];
    const float* Wo  = (const float*)d_in[8];
    const float* bo  = (const float*)d_in[9];
    float* out = (float*)d_out;

    int N   = in_sizes[1] / 4;
    int n_h = in_sizes[0] / F_DIM;
    int M   = 3 * N;

    __half *Y0, *h16, *P, *wt, *w1p;
    cudaGetSymbolAddress((void**)&Y0, g_Y0);
    cudaGetSymbolAddress((void**)&h16, g_h16);
    cudaGetSymbolAddress((void**)&P, g_P);
    cudaGetSymbolAddress((void**)&wt, g_Wt16);
    cudaGetSymbolAddress((void**)&w1p, g_W1P);
    __half* Wt2 = wt;
    __half* Wt3 = wt + H_DIM * H_DIM;

    cudaFuncSetAttribute(gemm_fused_kernel<0, 0>,
                         cudaFuncAttributeMaxDynamicSharedMemorySize, SMEM_TOTAL);
    cudaFuncSetAttribute(gemm_fused_kernel<1, 0>,
                         cudaFuncAttributeMaxDynamicSharedMemorySize, SMEM_TOTAL);
    cudaFuncSetAttribute(gemm_fused_kernel<0, 1>,
                         cudaFuncAttributeMaxDynamicSharedMemorySize, SMEM_TOTAL);

    detect_idx_kernel<<<1, 256>>>((const long long*)idx, n_h);

    int h4 = in_sizes[0] / 4;
    convert_h_kernel<<<(h4 + 255) / 256, 256>>>(h, h4);

    dim3 tb(32, 8), tg(16, 16);
    transposeW1_kernel<<<tg, tb>>>(W1, w1p);
    transpose512h_kernel<<<tg, tb>>>(W2, Wt2);
    transpose512h_kernel<<<tg, tb>>>(W3, Wt3);

    init_out_kernel<<<(N + 255) / 256, 256>>>(bo, out, N);

    // P = h16 @ W1P^T : [n_h,128] @ [2048,128]^T -> [n_h,2048]
    dim3 pgrid(2048 / 256, (n_h + 127) / 128);
    gemm_fused_kernel<0, 0><<<pgrid, 512, SMEM_TOTAL>>>(
        h16, w1p, nullptr, P, n_h, F_DIM, 2048, nullptr, nullptr, 0, nullptr, nullptr);

    int mtiles = (M + 127) / 128;
    dim3 ggrid(H_DIM / 256, mtiles);
    // layer 2: gathered A from P, output Y0
    gemm_fused_kernel<1, 0><<<ggrid, 512, SMEM_TOTAL>>>(
        nullptr, Wt2, b2, Y0, M, H_DIM, H_DIM, idx, b1, N, nullptr, nullptr);
    // layer 3: dense A = Y0, projection epilogue into out
    gemm_fused_kernel<0, 1><<<ggrid, 512, SMEM_TOTAL>>>(
        Y0, Wt3, b3, nullptr, M, H_DIM, H_DIM, nullptr, nullptr, N, Wo, out);
}

// round 8
// speedup vs baseline: 7.1515x; 1.0136x over previous
#include <cuda_runtime.h>
#include <cuda_fp16.h>
#include <cstdint>

// ---------------------------------------------------------------------------
// JanossyPoolingImproper — Round 8: n-grouped rows for gather locality,
// launch order tuned so ncu (-s 5) captures the gathered GEMM2.
//   P[node][j] = h[node] @ W1_block_j
//   GEMM2 (GATHER): A row (3n+p) = relu(sum_j P[idx[n,perm_p[j]]][j] + b1)
//   GEMM3 (PROJ):   epilogue relu(acc+b3) @ Wo -> atomicAdd(out[row/3])
// ---------------------------------------------------------------------------

#define H_DIM 512
#define F_DIM 128
#define MAX_N 100000
#define MAX_M (3 * MAX_N)
#define MAX_NH 50000
#define MAX_NH_PAD 50048

#define KC 32
#define ROWB 80
#define A_TILE (128 * ROWB)          // 10240
#define B_TILE (256 * ROWB)          // 20480
#define SM_B1OFF (3 * A_TILE + 3 * B_TILE)      // 92160
#define SM_POOFF (SM_B1OFF + 2048)              // 94208
#define SMEM_TOTAL (SM_POOFF + 1024)            // 95232

__constant__ int c_perms[3][4] = {{0,1,2,3},{2,1,3,0},{3,1,0,2}};

__device__ __half g_Y0[(size_t)MAX_M * H_DIM];
__device__ __half g_h16[(size_t)MAX_NH * F_DIM];
__device__ __half g_P[(size_t)MAX_NH_PAD * 2048];   // [node][j][512]
__device__ __half g_Wt16[2][H_DIM * H_DIM];         // W2^T, W3^T
__device__ __half g_W1P[2048 * F_DIM];              // [j*512+n][k]
__device__ int    g_idx64_flag;

// ---------------------------- helpers -------------------------------------
__device__ __forceinline__ uint32_t smem_u32(const void* p) {
    uint32_t a;
    asm("{ .reg .u64 t; cvta.to.shared.u64 t, %1; cvt.u32.u64 %0, t; }" : "=r"(a) : "l"(p));
    return a;
}
__device__ __forceinline__ void cp16(uint32_t dst, const void* src, bool pred) {
    int bytes = pred ? 16 : 0;
    asm volatile("cp.async.ca.shared.global [%0], [%1], 16, %2;"
                 :: "r"(dst), "l"(src), "r"(bytes) : "memory");
}
__device__ __forceinline__ void cp_commit() {
    asm volatile("cp.async.commit_group;" ::: "memory");
}
template <int N>
__device__ __forceinline__ void cp_wait() {
    asm volatile("cp.async.wait_group %0;" :: "n"(N) : "memory");
}
__device__ __forceinline__ void ldm_x4(uint32_t* r, uint32_t addr) {
    asm volatile("ldmatrix.sync.aligned.m8n8.x4.shared.b16 {%0,%1,%2,%3}, [%4];"
                 : "=r"(r[0]), "=r"(r[1]), "=r"(r[2]), "=r"(r[3]) : "r"(addr));
}
__device__ __forceinline__ void mma_fp16(float* c, const uint32_t* a, const uint32_t* b) {
    asm volatile(
        "mma.sync.aligned.m16n8k16.row.col.f32.f16.f16.f32 "
        "{%0,%1,%2,%3}, {%4,%5,%6,%7}, {%8,%9}, {%0,%1,%2,%3};"
        : "+f"(c[0]), "+f"(c[1]), "+f"(c[2]), "+f"(c[3])
        : "r"(a[0]), "r"(a[1]), "r"(a[2]), "r"(a[3]), "r"(b[0]), "r"(b[1]));
}

// ---------------------------------------------------------------------------
// Merged weight prep: z=0 -> W1 into W1P layout; z=1,2 -> W2/W3 into Wt (fp16).
__global__ void transpose_all_kernel(const float* __restrict__ W1,
                                     const float* __restrict__ W2,
                                     const float* __restrict__ W3,
                                     __half* __restrict__ W1P,
                                     __half* __restrict__ Wt2,
                                     __half* __restrict__ Wt3) {
    __shared__ float t[32][33];
    int z = blockIdx.z;
    const float* W = (z == 0) ? W1 : (z == 1) ? W2 : W3;
    int x = blockIdx.x * 32 + threadIdx.x;
    int y0 = blockIdx.y * 32;
#pragma unroll
    for (int i = threadIdx.y; i < 32; i += 8)
        t[i][threadIdx.x] = W[(y0 + i) * H_DIM + x];
    __syncthreads();
    if (z == 0) {
        int kprime = blockIdx.y * 32 + threadIdx.x;
        int j = kprime >> 7, kk = kprime & 127;
        int n0 = blockIdx.x * 32;
#pragma unroll
        for (int i = threadIdx.y; i < 32; i += 8)
            W1P[(size_t)(j * 512 + n0 + i) * F_DIM + kk] = __float2half_rn(t[threadIdx.x][i]);
    } else {
        __half* Wt = (z == 1) ? Wt2 : Wt3;
        int nx = blockIdx.y * 32 + threadIdx.x;
        int ny0 = blockIdx.x * 32;
#pragma unroll
        for (int i = threadIdx.y; i < 32; i += 8)
            Wt[(ny0 + i) * H_DIM + nx] = __float2half_rn(t[threadIdx.x][i]);
    }
}

__global__ void detect_idx_kernel(const long long* __restrict__ idx64, int n_h) {
    long long v = idx64[threadIdx.x];
    int ok = (v >= 0 && v < (long long)n_h) ? 1 : 0;
    int all = __syncthreads_and(ok);
    if (threadIdx.x == 0) g_idx64_flag = all;
}

__global__ void convert_h_kernel(const float* __restrict__ h, int total4) {
    int tid = blockIdx.x * blockDim.x + threadIdx.x;
    if (tid >= total4) return;
    float4 v = ((const float4*)h)[tid];
    ((__half2*)g_h16)[tid * 2 + 0] = __floats2half2_rn(v.x, v.y);
    ((__half2*)g_h16)[tid * 2 + 1] = __floats2half2_rn(v.z, v.w);
}

__global__ void init_out_kernel(const float* __restrict__ bo, float* __restrict__ out, int N) {
    int i = blockIdx.x * blockDim.x + threadIdx.x;
    if (i < N) {
        out[(size_t)i * 2 + 0] = __ldg(&bo[0]);
        out[(size_t)i * 2 + 1] = __ldg(&bo[1]);
    }
}

// ---------------------------------------------------------------------------
// Unified GEMM: C = (relu)(A[M,K] @ Wt^T + bias).  CTA 128x256, 512 thr,
// 16 warps 2(M)x8(N), warp tile 64x32, cp.async pipeline for B (+A if !GATHER).
// Row r of the big GEMMs encodes (sample n = r/3, perm p = r%3).
// GATHER: A row built on the fly from 4 gathered P segments (+b1, relu).
// PROJ:   no C store; epilogue computes relu(acc+bias) @ Wo -> atomicAdd(out).
// ---------------------------------------------------------------------------
template <int GATHER, int PROJ>
__global__ __launch_bounds__(512, 1) void gemm_fused_kernel(
    const __half* __restrict__ Ah, const __half* __restrict__ Wt,
    const float* __restrict__ bias, __half* __restrict__ C,
    int M, int K, int c_stride,
    const void* __restrict__ idx, const float* __restrict__ b1, int Nsamp,
    const float* __restrict__ Wo, float* __restrict__ out)
{
    extern __shared__ char smem[];
    uint32_t sA = smem_u32(smem);
    uint32_t sB = sA + 3 * A_TILE;
    float* b1s = (float*)(smem + SM_B1OFF);
    float* po  = (float*)(smem + SM_POOFF);
    int nstages = K / KC;

    int tid = threadIdx.x;
    int lane = tid & 31, wid = tid >> 5;
    int wm = wid >> 3, wn = wid & 7;
    int g = lane >> 2, t = lane & 3;
    int bn = blockIdx.x * 256;
    int bm = blockIdx.y * 128;

    int a_row = tid >> 2;
    int chunk = tid & 3;
    bool a_val = (bm + a_row) < M;

    // -------- gather-mode A producer state --------
    const __half* seg[4];
    uint4 areg[4];
    if (GATHER) {
        b1s[tid & 511] = b1[tid & 511];
        int row = a_val ? (bm + a_row) : 0;
        int n = row / 3;                 // n-grouped: row = 3n + p
        int p = row - 3 * n;
        long long node[4];
        if (g_idx64_flag) {
#pragma unroll
            for (int s = 0; s < 4; s++) node[s] = ((const long long*)idx)[(long long)n * 4 + s];
        } else {
#pragma unroll
            for (int s = 0; s < 4; s++) node[s] = (long long)((const int*)idx)[n * 4 + s];
        }
#pragma unroll
        for (int j = 0; j < 4; j++)
            seg[j] = g_P + node[c_perms[p][j]] * 2048 + j * 512 + chunk * 8;
#pragma unroll
        for (int j = 0; j < 4; j++) areg[j] = __ldg((const uint4*)(seg[j]));
    }

    auto load_B = [&](int s) {
        int buf = s % 3;
        int k0 = s * KC;
#pragma unroll
        for (int i = 0; i < 2; i++) {
            int row = (tid >> 2) + i * 128;
            uint32_t dst = sB + buf * B_TILE + (uint32_t)(row * ROWB + chunk * 16);
            cp16(dst, Wt + (size_t)(bn + row) * K + k0 + chunk * 8, true);
        }
    };
    auto load_A_cp = [&](int s) {
        int buf = s % 3;
        int k0 = s * KC;
        uint32_t dst = sA + buf * A_TILE + (uint32_t)(a_row * ROWB + chunk * 16);
        cp16(dst, Ah + (size_t)(bm + a_row) * K + k0 + chunk * 8, a_val);
    };

    if (!GATHER) load_A_cp(0);
    load_B(0); cp_commit();
    if (!GATHER) load_A_cp(1);
    load_B(1); cp_commit();
    if (GATHER) __syncthreads();   // b1s visible

    float acc[4][4][4];
#pragma unroll
    for (int i = 0; i < 4; i++)
#pragma unroll
        for (int j = 0; j < 4; j++)
#pragma unroll
            for (int r = 0; r < 4; r++) acc[i][j][r] = 0.0f;

    int a_row_off = (lane & 7) + ((lane >> 3) & 1) * 8;
    int a_col_off = (lane >> 4) * 8;
    int b_row_off = (lane & 7) + (lane >> 4) * 8;
    int b_col_off = ((lane >> 3) & 1) * 8;

    for (int s = 0; s < nstages; s++) {
        cp_wait<1>();
        if (GATHER) {
            int col0 = s * KC + chunk * 8;
            uint4 o;
            __half2* oh = (__half2*)&o;
#pragma unroll
            for (int i = 0; i < 4; i++) {
                float2 f0 = __half22float2(((const __half2*)&areg[0])[i]);
                float2 f1 = __half22float2(((const __half2*)&areg[1])[i]);
                float2 f2 = __half22float2(((const __half2*)&areg[2])[i]);
                float2 f3 = __half22float2(((const __half2*)&areg[3])[i]);
                float vx = f0.x + f1.x + f2.x + f3.x + b1s[col0 + 2 * i];
                float vy = f0.y + f1.y + f2.y + f3.y + b1s[col0 + 2 * i + 1];
                if (!a_val) { vx = 0.f; vy = 0.f; }
                oh[i] = __floats2half2_rn(fmaxf(vx, 0.f), fmaxf(vy, 0.f));
            }
            *(uint4*)(smem + (s & 1) * A_TILE + a_row * ROWB + chunk * 16) = o;
        }
        __syncthreads();
        if (GATHER && s + 1 < nstages) {
#pragma unroll
            for (int j = 0; j < 4; j++)
                areg[j] = __ldg((const uint4*)(seg[j] + (s + 1) * KC));
        }
        if (s + 2 < nstages) {
            if (!GATHER) load_A_cp(s + 2);
            load_B(s + 2);
            cp_commit();
        } else cp_commit();

        uint32_t aT = sA + (GATHER ? (s & 1) : (s % 3)) * A_TILE;
        uint32_t bT = sB + (s % 3) * B_TILE;
#pragma unroll
        for (int ks = 0; ks < 2; ks++) {
            int k = ks * 16;
            uint32_t af[4][4], bf[4][2];
#pragma unroll
            for (int mf = 0; mf < 4; mf++) {
                int row = wm * 64 + mf * 16 + a_row_off;
                ldm_x4(af[mf], aT + (uint32_t)(row * ROWB + (k + a_col_off) * 2));
            }
#pragma unroll
            for (int nfp = 0; nfp < 2; nfp++) {
                uint32_t r4[4];
                int row = wn * 32 + nfp * 16 + b_row_off;
                ldm_x4(r4, bT + (uint32_t)(row * ROWB + (k + b_col_off) * 2));
                bf[nfp * 2 + 0][0] = r4[0]; bf[nfp * 2 + 0][1] = r4[1];
                bf[nfp * 2 + 1][0] = r4[2]; bf[nfp * 2 + 1][1] = r4[3];
            }
#pragma unroll
            for (int mf = 0; mf < 4; mf++)
#pragma unroll
                for (int nf = 0; nf < 4; nf++)
                    mma_fp16(acc[mf][nf], af[mf], bf[nf]);
        }
    }

    if (PROJ) {
        // ---- projection epilogue: relu(acc + b3) @ Wo -> out (atomics) ----
        __syncthreads();
        if (tid < 256) po[tid] = 0.f;
        __syncthreads();
#pragma unroll
        for (int mf = 0; mf < 4; mf++) {
#pragma unroll
            for (int sub = 0; sub < 2; sub++) {
                float p0 = 0.f, p1 = 0.f;
#pragma unroll
                for (int nf = 0; nf < 4; nf++) {
                    int col = bn + wn * 32 + nf * 8 + 2 * t;
                    float2 b2 = *(const float2*)(bias + col);
                    float v0 = fmaxf(acc[mf][nf][sub * 2 + 0] + b2.x, 0.f);
                    float v1 = fmaxf(acc[mf][nf][sub * 2 + 1] + b2.y, 0.f);
                    p0 += v0 * __ldg(&Wo[col * 2 + 0]) + v1 * __ldg(&Wo[(col + 1) * 2 + 0]);
                    p1 += v0 * __ldg(&Wo[col * 2 + 1]) + v1 * __ldg(&Wo[(col + 1) * 2 + 1]);
                }
                p0 += __shfl_xor_sync(0xFFFFFFFFu, p0, 1);
                p0 += __shfl_xor_sync(0xFFFFFFFFu, p0, 2);
                p1 += __shfl_xor_sync(0xFFFFFFFFu, p1, 1);
                p1 += __shfl_xor_sync(0xFFFFFFFFu, p1, 2);
                if (t == 0) {
                    int rloc = wm * 64 + mf * 16 + sub * 8 + g;
                    atomicAdd(&po[rloc * 2 + 0], p0);
                    atomicAdd(&po[rloc * 2 + 1], p1);
                }
            }
        }
        __syncthreads();
        if (tid < 256) {
            int rloc = tid >> 1, comp = tid & 1;
            int row = bm + rloc;
            if (row < M) {
                int n = row / 3;       // n-grouped mapping
                atomicAdd(&out[(size_t)n * 2 + comp], po[rloc * 2 + comp]);
            }
        }
    } else {
#pragma unroll
        for (int nf = 0; nf < 4; nf++) {
            int col = bn + wn * 32 + nf * 8 + 2 * t;
            float2 b2 = bias ? *(const float2*)(bias + col) : make_float2(0.f, 0.f);
#pragma unroll
            for (int mf = 0; mf < 4; mf++) {
                int row0 = bm + wm * 64 + mf * 16 + g;
                float v0 = acc[mf][nf][0] + b2.x;
                float v1 = acc[mf][nf][1] + b2.y;
                float v2 = acc[mf][nf][2] + b2.x;
                float v3 = acc[mf][nf][3] + b2.y;
                if (bias) {
                    v0 = fmaxf(v0, 0.f); v1 = fmaxf(v1, 0.f);
                    v2 = fmaxf(v2, 0.f); v3 = fmaxf(v3, 0.f);
                }
                if (row0 < M)
                    *(__half2*)(C + (size_t)row0 * c_stride + col) = __floats2half2_rn(v0, v1);
                if (row0 + 8 < M)
                    *(__half2*)(C + (size_t)(row0 + 8) * c_stride + col) = __floats2half2_rn(v2, v3);
            }
        }
    }
}

// ---------------------------------------------------------------------------
extern "C" void kernel_launch(void* const* d_in, const int* in_sizes, int n_in,
                              void* d_out, int out_size) {
    const float* h   = (const float*)d_in[0];
    const void*  idx = d_in[1];
    const float* W1  = (const float*)d_in[2];
    const float* b1  = (const float*)d_in[3];
    const float* W2  = (const float*)d_in[4];
    const float* b2  = (const float*)d_in[5];
    const float* W3  = (const float*)d_in[6];
    const float* b3  = (const float*)d_in[7];
    const float* Wo  = (const float*)d_in[8];
    const float* bo  = (const float*)d_in[9];
    float* out = (float*)d_out;

    int N   = in_sizes[1] / 4;
    int n_h = in_sizes[0] / F_DIM;
    int M   = 3 * N;

    __half *Y0, *h16, *P, *wt, *w1p;
    cudaGetSymbolAddress((void**)&Y0, g_Y0);
    cudaGetSymbolAddress((void**)&h16, g_h16);
    cudaGetSymbolAddress((void**)&P, g_P);
    cudaGetSymbolAddress((void**)&wt, g_Wt16);
    cudaGetSymbolAddress((void**)&w1p, g_W1P);
    __half* Wt2 = wt;
    __half* Wt3 = wt + H_DIM * H_DIM;

    cudaFuncSetAttribute(gemm_fused_kernel<0, 0>,
                         cudaFuncAttributeMaxDynamicSharedMemorySize, SMEM_TOTAL);
    cudaFuncSetAttribute(gemm_fused_kernel<1, 0>,
                         cudaFuncAttributeMaxDynamicSharedMemorySize, SMEM_TOTAL);
    cudaFuncSetAttribute(gemm_fused_kernel<0, 1>,
                         cudaFuncAttributeMaxDynamicSharedMemorySize, SMEM_TOTAL);

    // Launch order chosen so ncu (-s 5 -c 1) captures launch #5 = GEMM2.
    dim3 tb(32, 8), tg(16, 16, 3);
    transpose_all_kernel<<<tg, tb>>>(W1, W2, W3, w1p, Wt2, Wt3);       // 1
    detect_idx_kernel<<<1, 256>>>((const long long*)idx, n_h);          // 2
    int h4 = in_sizes[0] / 4;
    convert_h_kernel<<<(h4 + 255) / 256, 256>>>(h, h4);                 // 3

    // 4: P = h16 @ W1P^T : [n_h,128] @ [2048,128]^T -> [n_h,2048]
    dim3 pgrid(2048 / 256, (n_h + 127) / 128);
    gemm_fused_kernel<0, 0><<<pgrid, 512, SMEM_TOTAL>>>(
        h16, w1p, nullptr, P, n_h, F_DIM, 2048, nullptr, nullptr, 0, nullptr, nullptr);

    // 5: layer 2 (gathered A from P) -> Y0
    int mtiles = (M + 127) / 128;
    dim3 ggrid(H_DIM / 256, mtiles);
    gemm_fused_kernel<1, 0><<<ggrid, 512, SMEM_TOTAL>>>(
        nullptr, Wt2, b2, Y0, M, H_DIM, H_DIM, idx, b1, N, nullptr, nullptr);

    init_out_kernel<<<(N + 255) / 256, 256>>>(bo, out, N);              // 6

    // 7: layer 3 (dense A = Y0), projection epilogue into out
    gemm_fused_kernel<0, 1><<<ggrid, 512, SMEM_TOTAL>>>(
        Y0, Wt3, b3, nullptr, M, H_DIM, H_DIM, nullptr, nullptr, N, Wo, out);
}